// round 5
// baseline (speedup 1.0000x reference)
#include <cuda_runtime.h>
#include <cuda.h>
#include <cuda_fp16.h>
#include <math.h>
#include <stdint.h>

// Problem constants
#define Bq 2
#define Sq 2048
#define Dq 1024
#define Fq 4096
#define Eq 8
#define Tq (Bq * Sq)            // 4096 tokens
#define Cq ((2 * 2 * Tq) / Eq)  // capacity = 2048
#define ROWS_TOT (Eq * Cq)      // 16384

// ---------------- scratch (device globals) --------------------------------
__device__ int    g_idx1[Tq];
__device__ int    g_idx2[Tq];
__device__ int    g_pos1[Tq];
__device__ int    g_pos2[Tq];
__device__ float  g_w1[Tq];
__device__ float  g_w2[Tq];
__device__ int    g_slot_token[ROWS_TOT];             // slot -> token (-1 empty)
__device__ __half g_xd [(size_t)ROWS_TOT * Dq];       // dispatched tokens fp16  32MB
__device__ __half g_w1t[(size_t)Eq * Fq * Dq];        // W1^T [E][F][D] fp16     64MB
__device__ __half g_w2t[(size_t)Eq * Dq * Fq];        // W2^T [E][D][F] fp16     64MB
__device__ __half g_h  [(size_t)ROWS_TOT * Fq];       // h fp16                 128MB
__device__ float  g_ye [(size_t)ROWS_TOT * Dq];       // ye fp32                 64MB

// ---------------- PTX helpers ----------------------------------------------
__device__ __forceinline__ uint32_t smem_u32(const void* p) {
    uint32_t a;
    asm("{ .reg .u64 t; cvta.to.shared.u64 t, %1; cvt.u32.u64 %0, t; }" : "=r"(a) : "l"(p));
    return a;
}

#define MBAR_INIT(a, c) \
    asm volatile("mbarrier.init.shared.b64 [%0], %1;" :: "r"(a), "r"(c) : "memory")
#define MBAR_EXPECT_TX(a, b) \
    asm volatile("mbarrier.arrive.expect_tx.shared.b64 _, [%0], %1;" :: "r"(a), "r"(b) : "memory")
#define MBAR_ARRIVE(a) \
    asm volatile("mbarrier.arrive.shared.b64 _, [%0];" :: "r"(a) : "memory")

#define MBAR_WAIT(mb, ph) do {                                                  \
    uint32_t _m = (mb); uint32_t _p = (ph);                                     \
    asm volatile("{\n\t.reg .pred P1;\n\t"                                      \
        "WL_%=:\n\t"                                                            \
        "mbarrier.try_wait.parity.acquire.cta.shared::cta.b64 P1, [%0], %1, 0x989680;\n\t" \
        "@P1 bra.uni WD_%=;\n\t"                                                \
        "bra.uni WL_%=;\n\t"                                                    \
        "WD_%=:\n\t}"                                                           \
        :: "r"(_m), "r"(_p) : "memory");                                        \
} while (0)

#define TMA_LD3D(smaddr, tmap, cx, cy, cz, mb)                                  \
    asm volatile("cp.async.bulk.tensor.3d.shared::cta.global.tile.mbarrier::complete_tx::bytes " \
        "[%0], [%1, {%2, %3, %4}], [%5];"                                       \
        :: "r"((uint32_t)(smaddr)), "l"(tmap), "r"((int)(cx)), "r"((int)(cy)),  \
           "r"((int)(cz)), "r"((uint32_t)(mb)) : "memory")

#define LDSM4(r0, r1, r2, r3, addr)                                             \
    asm volatile("ldmatrix.sync.aligned.m8n8.x4.shared.b16 {%0,%1,%2,%3}, [%4];" \
        : "=r"(r0), "=r"(r1), "=r"(r2), "=r"(r3) : "r"(addr))

#define MMA16816(c, a, b0, b1)                                                  \
    asm volatile("mma.sync.aligned.m16n8k16.row.col.f32.f16.f16.f32 "           \
        "{%0,%1,%2,%3}, {%4,%5,%6,%7}, {%8,%9}, {%0,%1,%2,%3};"                 \
        : "+f"((c)[0]), "+f"((c)[1]), "+f"((c)[2]), "+f"((c)[3])                \
        : "r"((a)[0]), "r"((a)[1]), "r"((a)[2]), "r"((a)[3]), "r"(b0), "r"(b1))

// ---------------- kernel 1: gating ----------------------------------------
__global__ void gate_kernel(const float* __restrict__ x,
                            const float* __restrict__ Wg) {
    int t = blockIdx.x * (blockDim.x >> 5) + (threadIdx.x >> 5);
    int lane = threadIdx.x & 31;
    if (t >= Tq) return;

    float acc[Eq];
#pragma unroll
    for (int e = 0; e < Eq; e++) acc[e] = 0.f;
    const float* xr = x + (size_t)t * Dq;
    for (int d = lane; d < Dq; d += 32) {
        float xv = xr[d];
        const float* wr = Wg + (size_t)d * Eq;
#pragma unroll
        for (int e = 0; e < Eq; e++) acc[e] += xv * wr[e];
    }
#pragma unroll
    for (int e = 0; e < Eq; e++)
#pragma unroll
        for (int off = 16; off > 0; off >>= 1)
            acc[e] += __shfl_xor_sync(0xffffffffu, acc[e], off);
    if (lane == 0) {
        int i1 = 0; float l1 = acc[0];
#pragma unroll
        for (int e = 1; e < Eq; e++) if (acc[e] > l1) { l1 = acc[e]; i1 = e; }
        int i2 = -1; float l2 = -3.4e38f;
#pragma unroll
        for (int e = 0; e < Eq; e++) if (e != i1 && acc[e] > l2) { l2 = acc[e]; i2 = e; }
        float s = 0.f, g[Eq];
#pragma unroll
        for (int e = 0; e < Eq; e++) { g[e] = expf(acc[e] - l1); s += g[e]; }
        float g1 = g[i1] / s, g2 = g[i2] / s;
        float denom = g1 + g2 + 1e-9f;
        g_idx1[t] = i1; g_idx2[t] = i2;
        g_w1[t] = g1 / denom; g_w2[t] = g2 / denom;
    }
}

// ---------------- kernel 2: per-expert ordered scan ------------------------
__global__ void scan_kernel() {
    const int e = blockIdx.x;
    const int tid = threadIdx.x;
    const int lane = tid & 31, wid = tid >> 5;
    __shared__ int wsum[32];
    __shared__ int s_total1;

    int* slot = g_slot_token + e * Cq;
    for (int s = tid; s < Cq; s += 1024) slot[s] = -1;
    __syncthreads();

    const int t0 = tid * 4;

    int m1[4], loc1[4], cnt = 0;
#pragma unroll
    for (int i = 0; i < 4; i++) { m1[i] = (g_idx1[t0 + i] == e); loc1[i] = cnt; cnt += m1[i]; }
    int v = cnt;
#pragma unroll
    for (int off = 1; off < 32; off <<= 1) {
        int u = __shfl_up_sync(0xffffffffu, v, off);
        if (lane >= off) v += u;
    }
    if (lane == 31) wsum[wid] = v;
    __syncthreads();
    if (wid == 0) {
        int w = wsum[lane];
#pragma unroll
        for (int off = 1; off < 32; off <<= 1) {
            int u = __shfl_up_sync(0xffffffffu, w, off);
            if (lane >= off) w += u;
        }
        wsum[lane] = w;
    }
    __syncthreads();
    int base = (v - cnt) + (wid ? wsum[wid - 1] : 0);
    if (tid == 0) s_total1 = wsum[31];
    __syncthreads();
#pragma unroll
    for (int i = 0; i < 4; i++) if (m1[i]) {
        int p = base + loc1[i];
        int t = t0 + i;
        if (p < Cq) { g_pos1[t] = p; slot[p] = t; }
        else        { g_pos1[t] = Cq - 1; g_w1[t] = 0.f; }
    }

    int m2[4], loc2[4]; cnt = 0;
#pragma unroll
    for (int i = 0; i < 4; i++) { m2[i] = (g_idx2[t0 + i] == e); loc2[i] = cnt; cnt += m2[i]; }
    v = cnt;
#pragma unroll
    for (int off = 1; off < 32; off <<= 1) {
        int u = __shfl_up_sync(0xffffffffu, v, off);
        if (lane >= off) v += u;
    }
    if (lane == 31) wsum[wid] = v;
    __syncthreads();
    if (wid == 0) {
        int w = wsum[lane];
#pragma unroll
        for (int off = 1; off < 32; off <<= 1) {
            int u = __shfl_up_sync(0xffffffffu, w, off);
            if (lane >= off) w += u;
        }
        wsum[lane] = w;
    }
    __syncthreads();
    int base2 = s_total1 + (v - cnt) + (wid ? wsum[wid - 1] : 0);
#pragma unroll
    for (int i = 0; i < 4; i++) if (m2[i]) {
        int p = base2 + loc2[i];
        int t = t0 + i;
        if (p < Cq) { g_pos2[t] = p; slot[p] = t; }
        else        { g_pos2[t] = Cq - 1; g_w2[t] = 0.f; }
    }
}

// ---------------- kernel 3: gather dispatched tokens -> fp16 ---------------
__global__ void gather_kernel(const float* __restrict__ x) {
    int row = blockIdx.x;               // 0..16383
    int tok = g_slot_token[row];
    __half2* o = (__half2*)(g_xd + (size_t)row * Dq);
    if (tok >= 0) {
        const float4* xi = (const float4*)(x + (size_t)tok * Dq);
        for (int i = threadIdx.x; i < Dq / 4; i += blockDim.x) {
            float4 v = xi[i];
            o[i * 2 + 0] = __floats2half2_rn(v.x, v.y);
            o[i * 2 + 1] = __floats2half2_rn(v.z, v.w);
        }
    } else {
        __half2 z = __floats2half2_rn(0.f, 0.f);
        for (int i = threadIdx.x; i < Dq / 4; i += blockDim.x) {
            o[i * 2 + 0] = z; o[i * 2 + 1] = z;
        }
    }
}

// ---------------- kernel 4: both weight transposes, one launch -------------
__global__ void transpose_all(const float* __restrict__ W1in,
                              const float* __restrict__ W2in,
                              __half* __restrict__ o1,
                              __half* __restrict__ o2) {
    __shared__ float t[64][65];
    const int z = blockIdx.z;
    const float* ip; __half* op; int R, Cc;
    if (z < Eq) { ip = W1in + (size_t)z * Dq * Fq;        op = o1 + (size_t)z * Dq * Fq;        R = Dq; Cc = Fq; }
    else        { ip = W2in + (size_t)(z - Eq) * Dq * Fq; op = o2 + (size_t)(z - Eq) * Dq * Fq; R = Fq; Cc = Dq; }
    const int c0 = blockIdx.x * 64, r0 = blockIdx.y * 64;
    if (c0 >= Cc || r0 >= R) return;
    const int tx = threadIdx.x, ty = threadIdx.y;   // 32 x 8

#pragma unroll
    for (int j = 0; j < 64; j += 8) {
        t[ty + j][tx]      = ip[(size_t)(r0 + ty + j) * Cc + c0 + tx];
        t[ty + j][tx + 32] = ip[(size_t)(r0 + ty + j) * Cc + c0 + tx + 32];
    }
    __syncthreads();
#pragma unroll
    for (int j = 0; j < 64; j += 8) {
        int cl = ty + j;
        __half2 v = __floats2half2_rn(t[2 * tx][cl], t[2 * tx + 1][cl]);
        *(__half2*)(op + (size_t)(c0 + cl) * R + r0 + 2 * tx) = v;
    }
}

// ---------------- fp16 mma.sync GEMM (128x128x128, warp-specialized) -------
// 8 consumer warps (2x4 tiling, 64x32 warp tile) + 1 producer warp.
// Stage = 64KB: A chunk0 | A chunk1 | B chunk0 | B chunk1 (each 16KB, 64-K wide).
// Out[row, col] = act( sum_k A[row,k] * B[e][col,k] + bias[e][col] )
template <int KT, bool GELU, typename OT, int NTOT>
__global__ void __launch_bounds__(288, 1)
gemm_mma(const __grid_constant__ CUtensorMap tmA,
         const __grid_constant__ CUtensorMap tmB,
         const float* __restrict__ bias, OT* __restrict__ Out) {
    constexpr int S = 3;
    constexpr int CH = 16384;              // one 64-K chunk: 128 rows x 128B
    constexpr int STAGE = 4 * CH;          // 64KB
    extern __shared__ __align__(1024) char smem[];
    const uint32_t sb = smem_u32(smem);
    const int tid = threadIdx.x;
    const int wid = tid >> 5, lane = tid & 31;
    const int row0 = blockIdx.y * 128;
    const int col0 = blockIdx.x * 128;
    const int e = row0 >> 11;              // row0 / 2048

    const uint32_t FULL0 = sb;             // full[s] = FULL0 + 16*s
    const uint32_t EMPT0 = sb + 8;         // empty[s] = EMPT0 + 16*s
    const uint32_t SDATA = sb + 1024;

    if (tid == 0) {
#pragma unroll
        for (int s = 0; s < S; s++) {
            MBAR_INIT(FULL0 + 16 * s, 1);
            MBAR_INIT(EMPT0 + 16 * s, 8);   // one arrive per consumer warp
        }
    }
    __syncthreads();

    if (wid == 8) {
        // ---------------- producer warp -------------------------------
        if (lane == 0) {
            int pph = 1;
#pragma unroll 1
            for (int j = 0; j < KT; j++) {
                const int st = j % S;
                MBAR_WAIT(EMPT0 + 16 * st, pph);
                if (st == S - 1) pph ^= 1;
                const uint32_t base = SDATA + st * STAGE;
                MBAR_EXPECT_TX(FULL0 + 16 * st, STAGE);
                TMA_LD3D(base + 0 * CH, &tmA, j * 128,      row0, 0, FULL0 + 16 * st);
                TMA_LD3D(base + 1 * CH, &tmA, j * 128 + 64, row0, 0, FULL0 + 16 * st);
                TMA_LD3D(base + 2 * CH, &tmB, j * 128,      col0, e, FULL0 + 16 * st);
                TMA_LD3D(base + 3 * CH, &tmB, j * 128 + 64, col0, e, FULL0 + 16 * st);
            }
        }
        return;                             // producer does no epilogue
    }

    // ---------------- consumer warps ----------------------------------
    const int warp_m = wid >> 2, warp_n = wid & 3;
    const int m0 = warp_m * 64, n0 = warp_n * 32;
    const uint32_t sw = (uint32_t)(lane & 7) << 4;   // SW128 xor

    uint32_t aoff[4], boff[2];
#pragma unroll
    for (int mi = 0; mi < 4; mi++)
        aoff[mi] = (uint32_t)(m0 + mi * 16 + (lane & 15)) * 128;
#pragma unroll
    for (int p = 0; p < 2; p++)
        boff[p] = (uint32_t)(n0 + (2 * p + ((lane >> 4) & 1)) * 8 + (lane & 7)) * 128;
    const uint32_t kxA = ((lane >> 4) & 1) * 16;
    const uint32_t kxB = ((lane >> 3) & 1) * 16;

    float acc[4][4][4];
#pragma unroll
    for (int mi = 0; mi < 4; mi++)
#pragma unroll
        for (int ni = 0; ni < 4; ni++)
#pragma unroll
            for (int q = 0; q < 4; q++) acc[mi][ni][q] = 0.f;

#pragma unroll 1
    for (int kt = 0; kt < KT; kt++) {
        const int st = kt % S;
        MBAR_WAIT(FULL0 + 16 * st, (kt / S) & 1);

        const uint32_t base = SDATA + st * STAGE;
#pragma unroll
        for (int kk = 0; kk < 8; kk++) {
            const uint32_t co = (uint32_t)(kk >> 2) * CH;      // chunk offset
            const uint32_t kg = (uint32_t)(kk & 3) * 32;       // k-group bytes
            const uint32_t ka = (kg + kxA) ^ sw;
            const uint32_t kb = (kg + kxB) ^ sw;
            const uint32_t sa  = base + co;
            const uint32_t sbB = base + 2 * CH + co;
            uint32_t a[4][4], b[4][2];
#pragma unroll
            for (int mi = 0; mi < 4; mi++)
                LDSM4(a[mi][0], a[mi][1], a[mi][2], a[mi][3], sa + aoff[mi] + ka);
#pragma unroll
            for (int p = 0; p < 2; p++) {
                uint32_t r0, r1, r2, r3;
                LDSM4(r0, r1, r2, r3, sbB + boff[p] + kb);
                b[2 * p][0] = r0; b[2 * p][1] = r1;
                b[2 * p + 1][0] = r2; b[2 * p + 1][1] = r3;
            }
#pragma unroll
            for (int mi = 0; mi < 4; mi++)
#pragma unroll
                for (int ni = 0; ni < 4; ni++)
                    MMA16816(acc[mi][ni], a[mi], b[ni][0], b[ni][1]);
        }
        if (lane == 0) MBAR_ARRIVE(EMPT0 + 16 * st);
    }

    // ---------------- epilogue ------------------------------------------
    const float* brow = bias + (size_t)e * NTOT;
#pragma unroll
    for (int mi = 0; mi < 4; mi++) {
#pragma unroll
        for (int ni = 0; ni < 4; ni++) {
            int col = col0 + n0 + ni * 8 + (lane & 3) * 2;
            float bz0 = brow[col], bz1 = brow[col + 1];
#pragma unroll
            for (int h = 0; h < 2; h++) {
                int row = row0 + m0 + mi * 16 + (lane >> 2) + h * 8;
                float v0 = acc[mi][ni][2 * h + 0] + bz0;
                float v1 = acc[mi][ni][2 * h + 1] + bz1;
                if (GELU) {
                    v0 = 0.5f * v0 * (1.f + erff(v0 * 0.70710678118654752f));
                    v1 = 0.5f * v1 * (1.f + erff(v1 * 0.70710678118654752f));
                }
                if (sizeof(OT) == 2) {
                    *(__half2*)((__half*)Out + (size_t)row * NTOT + col) =
                        __floats2half2_rn(v0, v1);
                } else {
                    *(float2*)((float*)Out + (size_t)row * NTOT + col) =
                        make_float2(v0, v1);
                }
            }
        }
    }
}

// ---------------- kernel 7: combine ----------------------------------------
__global__ void combine_kernel(float* __restrict__ out) {
    int t = blockIdx.x;
    int i1 = g_idx1[t], i2 = g_idx2[t];
    float w1 = g_w1[t], w2 = g_w2[t];
    const float4* y1 = (const float4*)(g_ye + ((size_t)i1 * Cq + g_pos1[t]) * Dq);
    const float4* y2 = (const float4*)(g_ye + ((size_t)i2 * Cq + g_pos2[t]) * Dq);
    float4* o = (float4*)(out + (size_t)t * Dq);
    for (int j = threadIdx.x; j < Dq / 4; j += blockDim.x) {
        float4 a = y1[j], b = y2[j];
        float4 r;
        r.x = w1 * a.x + w2 * b.x;
        r.y = w1 * a.y + w2 * b.y;
        r.z = w1 * a.z + w2 * b.z;
        r.w = w1 * a.w + w2 * b.w;
        o[j] = r;
    }
}

// ---------------- host: tensor-map build + launch ---------------------------
typedef CUresult (*EncodeFn)(CUtensorMap*, CUtensorMapDataType, cuuint32_t, void*,
                             const cuuint64_t*, const cuuint64_t*, const cuuint32_t*,
                             const cuuint32_t*, CUtensorMapInterleave, CUtensorMapSwizzle,
                             CUtensorMapL2promotion, CUtensorMapFloatOOBfill);

static void enc_map(EncodeFn fn, CUtensorMap* m, void* p,
                    uint64_t d0, uint64_t d1, uint64_t d2) {
    cuuint64_t dims[3] = {d0, d1, d2};
    cuuint64_t str[2] = {d0 * 2, d0 * d1 * 2};   // fp16
    cuuint32_t box[3] = {64, 128, 1};            // 64 fp16 = 128B rows
    cuuint32_t es[3] = {1, 1, 1};
    fn(m, CU_TENSOR_MAP_DATA_TYPE_FLOAT16, 3, p, dims, str, box, es,
       CU_TENSOR_MAP_INTERLEAVE_NONE, CU_TENSOR_MAP_SWIZZLE_128B,
       CU_TENSOR_MAP_L2_PROMOTION_L2_128B, CU_TENSOR_MAP_FLOAT_OOB_FILL_NONE);
}

extern "C" void kernel_launch(void* const* d_in, const int* in_sizes, int n_in,
                              void* d_out, int out_size) {
    const float* x  = (const float*)d_in[0];
    const float* Wg = (const float*)d_in[1];
    const float* W1 = (const float*)d_in[2];
    const float* b1 = (const float*)d_in[3];
    const float* W2 = (const float*)d_in[4];
    const float* b2 = (const float*)d_in[5];
    float* out = (float*)d_out;

    __half *xd, *w1t, *w2t, *hbuf;
    float* yebuf;
    cudaGetSymbolAddress((void**)&xd,    g_xd);
    cudaGetSymbolAddress((void**)&w1t,   g_w1t);
    cudaGetSymbolAddress((void**)&w2t,   g_w2t);
    cudaGetSymbolAddress((void**)&hbuf,  g_h);
    cudaGetSymbolAddress((void**)&yebuf, g_ye);

    EncodeFn enc = nullptr;
    {
        void* fp = nullptr;
        cudaDriverEntryPointQueryResult qr;
        cudaGetDriverEntryPointByVersion("cuTensorMapEncodeTiled", &fp, 12000,
                                         cudaEnableDefault, &qr);
        enc = (EncodeFn)fp;
    }

    CUtensorMap tmA1, tmB1, tmA2, tmB2;
    enc_map(enc, &tmA1, xd,   Dq, ROWS_TOT, 1);   // [16384,1024] fp16
    enc_map(enc, &tmB1, w1t,  Dq, Fq, Eq);        // [E][4096][1024]
    enc_map(enc, &tmA2, hbuf, Fq, ROWS_TOT, 1);   // [16384,4096]
    enc_map(enc, &tmB2, w2t,  Fq, Dq, Eq);        // [E][1024][4096]

    constexpr int SMEM_SZ = 1024 + 3 * 4 * 16384;  // 197632 (193KB)
    cudaFuncSetAttribute(gemm_mma<Dq / 128, true, __half, Fq>,
                         cudaFuncAttributeMaxDynamicSharedMemorySize, SMEM_SZ);
    cudaFuncSetAttribute(gemm_mma<Fq / 128, false, float, Dq>,
                         cudaFuncAttributeMaxDynamicSharedMemorySize, SMEM_SZ);

    // 1) gating
    gate_kernel<<<Tq / 4, 128>>>(x, Wg);
    // 2) ordered per-expert scan
    scan_kernel<<<Eq, 1024>>>();
    // 3) gather dispatched tokens (fp16)
    gather_kernel<<<ROWS_TOT, 128>>>(x);
    // 4) both weight transposes in ONE launch
    {
        dim3 blk(32, 8);
        transpose_all<<<dim3(Fq / 64, Fq / 64, 2 * Eq), blk>>>(W1, W2, w1t, w2t);
    }
    // 5) GEMM1: h = gelu(xd @ W1^T + b1)   [16384, 4096] fp16
    gemm_mma<Dq / 128, true, __half, Fq>
        <<<dim3(Fq / 128, ROWS_TOT / 128), 288, SMEM_SZ>>>(tmA1, tmB1, b1, hbuf);
    // 6) GEMM2: ye = h @ W2^T + b2         [16384, 1024] fp32
    gemm_mma<Fq / 128, false, float, Dq>
        <<<dim3(Dq / 128, ROWS_TOT / 128), 288, SMEM_SZ>>>(tmA2, tmB2, b2, yebuf);
    // 7) combine
    combine_kernel<<<Tq, 256>>>(out);
}

// round 7
// speedup vs baseline: 1.4050x; 1.4050x over previous
#include <cuda_runtime.h>
#include <cuda.h>
#include <cuda_fp16.h>
#include <math.h>
#include <stdint.h>

// Problem constants
#define Bq 2
#define Sq 2048
#define Dq 1024
#define Fq 4096
#define Eq 8
#define Tq (Bq * Sq)            // 4096 tokens
#define Cq ((2 * 2 * Tq) / Eq)  // capacity = 2048
#define ROWS_TOT (Eq * Cq)      // 16384

// ---------------- scratch (device globals) --------------------------------
__device__ int    g_idx1[Tq];
__device__ int    g_idx2[Tq];
__device__ int    g_pos1[Tq];
__device__ int    g_pos2[Tq];
__device__ float  g_w1[Tq];
__device__ float  g_w2[Tq];
__device__ int    g_slot_token[ROWS_TOT];             // slot -> token (-1 empty)
__device__ __half g_xd [(size_t)ROWS_TOT * Dq];       // dispatched tokens fp16  32MB
__device__ __half g_w1t[(size_t)Eq * Fq * Dq];        // W1^T [E][F][D] fp16     64MB
__device__ __half g_w2t[(size_t)Eq * Dq * Fq];        // W2^T [E][D][F] fp16     64MB
__device__ __half g_h  [(size_t)ROWS_TOT * Fq];       // h fp16                 128MB
__device__ float  g_ye [(size_t)ROWS_TOT * Dq];       // ye fp32                 64MB

// ---------------- PTX helpers ----------------------------------------------
__device__ __forceinline__ uint32_t smem_u32(const void* p) {
    uint32_t a;
    asm("{ .reg .u64 t; cvta.to.shared.u64 t, %1; cvt.u32.u64 %0, t; }" : "=r"(a) : "l"(p));
    return a;
}

#define MBAR_INIT(a, c) \
    asm volatile("mbarrier.init.shared.b64 [%0], %1;" :: "r"(a), "r"(c) : "memory")
#define MBAR_EXPECT_TX(a, b) \
    asm volatile("mbarrier.arrive.expect_tx.shared.b64 _, [%0], %1;" :: "r"(a), "r"(b) : "memory")
#define MBAR_ARRIVE(a) \
    asm volatile("mbarrier.arrive.shared.b64 _, [%0];" :: "r"(a) : "memory")
#define FENCE_PROXY_ASYNC() \
    asm volatile("fence.proxy.async.shared::cta;" ::: "memory")

#define MBAR_WAIT(mb, ph) do {                                                  \
    uint32_t _m = (mb); uint32_t _p = (ph);                                     \
    asm volatile("{\n\t.reg .pred P1;\n\t"                                      \
        "WL_%=:\n\t"                                                            \
        "mbarrier.try_wait.parity.acquire.cta.shared::cta.b64 P1, [%0], %1, 0x989680;\n\t" \
        "@P1 bra.uni WD_%=;\n\t"                                                \
        "bra.uni WL_%=;\n\t"                                                    \
        "WD_%=:\n\t}"                                                           \
        :: "r"(_m), "r"(_p) : "memory");                                        \
} while (0)

#define TMA_LD3D(smaddr, tmap, cx, cy, cz, mb)                                  \
    asm volatile("cp.async.bulk.tensor.3d.shared::cta.global.tile.mbarrier::complete_tx::bytes " \
        "[%0], [%1, {%2, %3, %4}], [%5];"                                       \
        :: "r"((uint32_t)(smaddr)), "l"(tmap), "r"((int)(cx)), "r"((int)(cy)),  \
           "r"((int)(cz)), "r"((uint32_t)(mb)) : "memory")

#define LDSM4(r0, r1, r2, r3, addr)                                             \
    asm volatile("ldmatrix.sync.aligned.m8n8.x4.shared.b16 {%0,%1,%2,%3}, [%4];" \
        : "=r"(r0), "=r"(r1), "=r"(r2), "=r"(r3) : "r"(addr))

#define MMA16816(c, a, b0, b1)                                                  \
    asm volatile("mma.sync.aligned.m16n8k16.row.col.f32.f16.f16.f32 "           \
        "{%0,%1,%2,%3}, {%4,%5,%6,%7}, {%8,%9}, {%0,%1,%2,%3};"                 \
        : "+f"((c)[0]), "+f"((c)[1]), "+f"((c)[2]), "+f"((c)[3])                \
        : "r"((a)[0]), "r"((a)[1]), "r"((a)[2]), "r"((a)[3]), "r"(b0), "r"(b1))

// ---------------- kernel 1: gating ----------------------------------------
__global__ void gate_kernel(const float* __restrict__ x,
                            const float* __restrict__ Wg) {
    int t = blockIdx.x * (blockDim.x >> 5) + (threadIdx.x >> 5);
    int lane = threadIdx.x & 31;
    if (t >= Tq) return;

    float acc[Eq];
#pragma unroll
    for (int e = 0; e < Eq; e++) acc[e] = 0.f;
    const float* xr = x + (size_t)t * Dq;
    for (int d = lane; d < Dq; d += 32) {
        float xv = xr[d];
        const float* wr = Wg + (size_t)d * Eq;
#pragma unroll
        for (int e = 0; e < Eq; e++) acc[e] += xv * wr[e];
    }
#pragma unroll
    for (int e = 0; e < Eq; e++)
#pragma unroll
        for (int off = 16; off > 0; off >>= 1)
            acc[e] += __shfl_xor_sync(0xffffffffu, acc[e], off);
    if (lane == 0) {
        int i1 = 0; float l1 = acc[0];
#pragma unroll
        for (int e = 1; e < Eq; e++) if (acc[e] > l1) { l1 = acc[e]; i1 = e; }
        int i2 = -1; float l2 = -3.4e38f;
#pragma unroll
        for (int e = 0; e < Eq; e++) if (e != i1 && acc[e] > l2) { l2 = acc[e]; i2 = e; }
        float s = 0.f, g[Eq];
#pragma unroll
        for (int e = 0; e < Eq; e++) { g[e] = expf(acc[e] - l1); s += g[e]; }
        float g1 = g[i1] / s, g2 = g[i2] / s;
        float denom = g1 + g2 + 1e-9f;
        g_idx1[t] = i1; g_idx2[t] = i2;
        g_w1[t] = g1 / denom; g_w2[t] = g2 / denom;
    }
}

// ---------------- kernel 2: per-expert ordered scan ------------------------
__global__ void scan_kernel() {
    const int e = blockIdx.x;
    const int tid = threadIdx.x;
    const int lane = tid & 31, wid = tid >> 5;
    __shared__ int wsum[32];
    __shared__ int s_total1;

    int* slot = g_slot_token + e * Cq;
    for (int s = tid; s < Cq; s += 1024) slot[s] = -1;
    __syncthreads();

    const int t0 = tid * 4;

    int m1[4], loc1[4], cnt = 0;
#pragma unroll
    for (int i = 0; i < 4; i++) { m1[i] = (g_idx1[t0 + i] == e); loc1[i] = cnt; cnt += m1[i]; }
    int v = cnt;
#pragma unroll
    for (int off = 1; off < 32; off <<= 1) {
        int u = __shfl_up_sync(0xffffffffu, v, off);
        if (lane >= off) v += u;
    }
    if (lane == 31) wsum[wid] = v;
    __syncthreads();
    if (wid == 0) {
        int w = wsum[lane];
#pragma unroll
        for (int off = 1; off < 32; off <<= 1) {
            int u = __shfl_up_sync(0xffffffffu, w, off);
            if (lane >= off) w += u;
        }
        wsum[lane] = w;
    }
    __syncthreads();
    int base = (v - cnt) + (wid ? wsum[wid - 1] : 0);
    if (tid == 0) s_total1 = wsum[31];
    __syncthreads();
#pragma unroll
    for (int i = 0; i < 4; i++) if (m1[i]) {
        int p = base + loc1[i];
        int t = t0 + i;
        if (p < Cq) { g_pos1[t] = p; slot[p] = t; }
        else        { g_pos1[t] = Cq - 1; g_w1[t] = 0.f; }
    }

    int m2[4], loc2[4]; cnt = 0;
#pragma unroll
    for (int i = 0; i < 4; i++) { m2[i] = (g_idx2[t0 + i] == e); loc2[i] = cnt; cnt += m2[i]; }
    v = cnt;
#pragma unroll
    for (int off = 1; off < 32; off <<= 1) {
        int u = __shfl_up_sync(0xffffffffu, v, off);
        if (lane >= off) v += u;
    }
    if (lane == 31) wsum[wid] = v;
    __syncthreads();
    if (wid == 0) {
        int w = wsum[lane];
#pragma unroll
        for (int off = 1; off < 32; off <<= 1) {
            int u = __shfl_up_sync(0xffffffffu, w, off);
            if (lane >= off) w += u;
        }
        wsum[lane] = w;
    }
    __syncthreads();
    int base2 = s_total1 + (v - cnt) + (wid ? wsum[wid - 1] : 0);
#pragma unroll
    for (int i = 0; i < 4; i++) if (m2[i]) {
        int p = base2 + loc2[i];
        int t = t0 + i;
        if (p < Cq) { g_pos2[t] = p; slot[p] = t; }
        else        { g_pos2[t] = Cq - 1; g_w2[t] = 0.f; }
    }
}

// ---------------- kernel 3: gather dispatched tokens -> fp16 ---------------
__global__ void gather_kernel(const float* __restrict__ x) {
    int row = blockIdx.x;               // 0..16383
    int tok = g_slot_token[row];
    __half2* o = (__half2*)(g_xd + (size_t)row * Dq);
    if (tok >= 0) {
        const float4* xi = (const float4*)(x + (size_t)tok * Dq);
        for (int i = threadIdx.x; i < Dq / 4; i += blockDim.x) {
            float4 v = xi[i];
            o[i * 2 + 0] = __floats2half2_rn(v.x, v.y);
            o[i * 2 + 1] = __floats2half2_rn(v.z, v.w);
        }
    } else {
        __half2 z = __floats2half2_rn(0.f, 0.f);
        for (int i = threadIdx.x; i < Dq / 4; i += blockDim.x) {
            o[i * 2 + 0] = z; o[i * 2 + 1] = z;
        }
    }
}

// ---------------- kernel 4: weight transpose fp32 -> fp16 ------------------
// in [E][R][Cc] -> out [E][Cc][R], exact grid per matrix
__global__ void transpose_k(const float* __restrict__ in, __half* __restrict__ outp,
                            int R, int Cc) {
    __shared__ float t[64][65];
    const int e = blockIdx.z;
    const float* ip = in + (size_t)e * R * Cc;
    __half* op = outp + (size_t)e * R * Cc;
    const int c0 = blockIdx.x * 64, r0 = blockIdx.y * 64;
    const int tx = threadIdx.x, ty = threadIdx.y;   // 32 x 8

#pragma unroll
    for (int j = 0; j < 64; j += 8) {
        t[ty + j][tx]      = ip[(size_t)(r0 + ty + j) * Cc + c0 + tx];
        t[ty + j][tx + 32] = ip[(size_t)(r0 + ty + j) * Cc + c0 + tx + 32];
    }
    __syncthreads();
#pragma unroll
    for (int j = 0; j < 64; j += 8) {
        int cl = ty + j;
        __half2 v = __floats2half2_rn(t[2 * tx][cl], t[2 * tx + 1][cl]);
        *(__half2*)(op + (size_t)(c0 + cl) * R + r0 + 2 * tx) = v;
    }
}

// ---------------- fp16 mma.sync GEMM (128x128x64, TMA 3-stage) -------------
// Round-4 structure; refill hoisted to iteration top waiting the PREVIOUS
// iteration's empty phase (decouples warp 0 from current-iter stragglers).
template <int KT, bool GELU, typename OT, int NTOT>
__global__ void __launch_bounds__(256, 1)
gemm_mma(const __grid_constant__ CUtensorMap tmA,
         const __grid_constant__ CUtensorMap tmB,
         const float* __restrict__ bias, OT* __restrict__ Out) {
    constexpr int S = 3;
    constexpr int TILE_B = 16384;          // 128 rows x 128B (64 fp16)
    extern __shared__ __align__(1024) char smem[];
    const uint32_t sb = smem_u32(smem);
    const int tid = threadIdx.x;
    const int wid = tid >> 5, lane = tid & 31;
    const int row0 = blockIdx.y * 128;
    const int col0 = blockIdx.x * 128;
    const int e = row0 >> 11;              // row0 / 2048

    const uint32_t FULL0 = sb;             // full[s] = FULL0 + 16*s
    const uint32_t EMPT0 = sb + 8;         // empty[s] = EMPT0 + 16*s
    const uint32_t SA = sb + 1024;
    const uint32_t SB_ = sb + 1024 + S * TILE_B;

    if (tid == 0) {
#pragma unroll
        for (int s = 0; s < S; s++) {
            MBAR_INIT(FULL0 + 16 * s, 1);
            MBAR_INIT(EMPT0 + 16 * s, 8);   // one arrive per warp
        }
        FENCE_PROXY_ASYNC();                // order init before async-proxy TMA
    }
    __syncthreads();

    // warp tiling: 2 (M) x 4 (N); warp tile 64 x 32
    const int warp_m = wid >> 2, warp_n = wid & 3;
    const int m0 = warp_m * 64, n0 = warp_n * 32;
    const uint32_t sw = (uint32_t)(lane & 7) << 4;   // SW128 xor

    uint32_t aoff[4], boff[2];
#pragma unroll
    for (int mi = 0; mi < 4; mi++)
        aoff[mi] = (uint32_t)(m0 + mi * 16 + (lane & 15)) * 128;
#pragma unroll
    for (int p = 0; p < 2; p++)
        boff[p] = (uint32_t)(n0 + (2 * p + ((lane >> 4) & 1)) * 8 + (lane & 7)) * 128;
    const uint32_t kxA = ((lane >> 4) & 1) * 16;
    const uint32_t kxB = ((lane >> 3) & 1) * 16;

    float acc[4][4][4];
#pragma unroll
    for (int mi = 0; mi < 4; mi++)
#pragma unroll
        for (int ni = 0; ni < 4; ni++)
#pragma unroll
            for (int q = 0; q < 4; q++) acc[mi][ni][q] = 0.f;

    if (tid == 0) {
#pragma unroll
        for (int s = 0; s < S && s < KT; s++) {
            MBAR_EXPECT_TX(FULL0 + 16 * s, 2 * TILE_B);
            TMA_LD3D(SA + s * TILE_B, &tmA, s * 64, row0, 0, FULL0 + 16 * s);
            TMA_LD3D(SB_ + s * TILE_B, &tmB, s * 64, col0, e, FULL0 + 16 * s);
        }
    }

#pragma unroll 1
    for (int kt = 0; kt < KT; kt++) {
        const int st = kt % S;
        MBAR_WAIT(FULL0 + 16 * st, (kt / S) & 1);

        // refill: issue load for j = kt+S-1 into stage (kt-1)%S, gated on the
        // PREVIOUS iteration's consumption (arrives from kt-1 -> nearly free).
        if (tid == 0 && kt >= 1) {
            const int j = kt + S - 1;
            if (j < KT) {
                const int st2 = (kt - 1) % S;
                MBAR_WAIT(EMPT0 + 16 * st2, ((kt - 1) / S) & 1);
                MBAR_EXPECT_TX(FULL0 + 16 * st2, 2 * TILE_B);
                TMA_LD3D(SA + st2 * TILE_B, &tmA, j * 64, row0, 0, FULL0 + 16 * st2);
                TMA_LD3D(SB_ + st2 * TILE_B, &tmB, j * 64, col0, e, FULL0 + 16 * st2);
            }
        }

        const uint32_t sa = SA + st * TILE_B;
        const uint32_t sbB = SB_ + st * TILE_B;
#pragma unroll
        for (int kk = 0; kk < 4; kk++) {
            const uint32_t ka = ((uint32_t)(kk * 32) + kxA) ^ sw;
            const uint32_t kb = ((uint32_t)(kk * 32) + kxB) ^ sw;
            uint32_t a[4][4], b[4][2];
#pragma unroll
            for (int mi = 0; mi < 4; mi++)
                LDSM4(a[mi][0], a[mi][1], a[mi][2], a[mi][3], sa + aoff[mi] + ka);
#pragma unroll
            for (int p = 0; p < 2; p++) {
                uint32_t r0, r1, r2, r3;
                LDSM4(r0, r1, r2, r3, sbB + boff[p] + kb);
                b[2 * p][0] = r0; b[2 * p][1] = r1;
                b[2 * p + 1][0] = r2; b[2 * p + 1][1] = r3;
            }
#pragma unroll
            for (int mi = 0; mi < 4; mi++)
#pragma unroll
                for (int ni = 0; ni < 4; ni++)
                    MMA16816(acc[mi][ni], a[mi], b[ni][0], b[ni][1]);
        }
        if (lane == 0) MBAR_ARRIVE(EMPT0 + 16 * st);
    }

    // ---------------- epilogue ------------------------------------------
    const float* brow = bias + (size_t)e * NTOT;
#pragma unroll
    for (int mi = 0; mi < 4; mi++) {
#pragma unroll
        for (int ni = 0; ni < 4; ni++) {
            int col = col0 + n0 + ni * 8 + (lane & 3) * 2;
            float bz0 = brow[col], bz1 = brow[col + 1];
#pragma unroll
            for (int h = 0; h < 2; h++) {
                int row = row0 + m0 + mi * 16 + (lane >> 2) + h * 8;
                float v0 = acc[mi][ni][2 * h + 0] + bz0;
                float v1 = acc[mi][ni][2 * h + 1] + bz1;
                if (GELU) {
                    v0 = 0.5f * v0 * (1.f + erff(v0 * 0.70710678118654752f));
                    v1 = 0.5f * v1 * (1.f + erff(v1 * 0.70710678118654752f));
                }
                if (sizeof(OT) == 2) {
                    *(__half2*)((__half*)Out + (size_t)row * NTOT + col) =
                        __floats2half2_rn(v0, v1);
                } else {
                    *(float2*)((float*)Out + (size_t)row * NTOT + col) =
                        make_float2(v0, v1);
                }
            }
        }
    }
}

// ---------------- kernel 7: combine ----------------------------------------
__global__ void combine_kernel(float* __restrict__ out) {
    int t = blockIdx.x;
    int i1 = g_idx1[t], i2 = g_idx2[t];
    float w1 = g_w1[t], w2 = g_w2[t];
    const float4* y1 = (const float4*)(g_ye + ((size_t)i1 * Cq + g_pos1[t]) * Dq);
    const float4* y2 = (const float4*)(g_ye + ((size_t)i2 * Cq + g_pos2[t]) * Dq);
    float4* o = (float4*)(out + (size_t)t * Dq);
    for (int j = threadIdx.x; j < Dq / 4; j += blockDim.x) {
        float4 a = y1[j], b = y2[j];
        float4 r;
        r.x = w1 * a.x + w2 * b.x;
        r.y = w1 * a.y + w2 * b.y;
        r.z = w1 * a.z + w2 * b.z;
        r.w = w1 * a.w + w2 * b.w;
        o[j] = r;
    }
}

// ---------------- host: tensor-map build + launch ---------------------------
typedef CUresult (*EncodeFn)(CUtensorMap*, CUtensorMapDataType, cuuint32_t, void*,
                             const cuuint64_t*, const cuuint64_t*, const cuuint32_t*,
                             const cuuint32_t*, CUtensorMapInterleave, CUtensorMapSwizzle,
                             CUtensorMapL2promotion, CUtensorMapFloatOOBfill);

static void enc_map(EncodeFn fn, CUtensorMap* m, void* p,
                    uint64_t d0, uint64_t d1, uint64_t d2) {
    cuuint64_t dims[3] = {d0, d1, d2};
    cuuint64_t str[2] = {d0 * 2, d0 * d1 * 2};   // fp16
    cuuint32_t box[3] = {64, 128, 1};            // 64 fp16 = 128B rows
    cuuint32_t es[3] = {1, 1, 1};
    fn(m, CU_TENSOR_MAP_DATA_TYPE_FLOAT16, 3, p, dims, str, box, es,
       CU_TENSOR_MAP_INTERLEAVE_NONE, CU_TENSOR_MAP_SWIZZLE_128B,
       CU_TENSOR_MAP_L2_PROMOTION_L2_128B, CU_TENSOR_MAP_FLOAT_OOB_FILL_NONE);
}

extern "C" void kernel_launch(void* const* d_in, const int* in_sizes, int n_in,
                              void* d_out, int out_size) {
    const float* x  = (const float*)d_in[0];
    const float* Wg = (const float*)d_in[1];
    const float* W1 = (const float*)d_in[2];
    const float* b1 = (const float*)d_in[3];
    const float* W2 = (const float*)d_in[4];
    const float* b2 = (const float*)d_in[5];
    float* out = (float*)d_out;

    __half *xd, *w1t, *w2t, *hbuf;
    float* yebuf;
    cudaGetSymbolAddress((void**)&xd,    g_xd);
    cudaGetSymbolAddress((void**)&w1t,   g_w1t);
    cudaGetSymbolAddress((void**)&w2t,   g_w2t);
    cudaGetSymbolAddress((void**)&hbuf,  g_h);
    cudaGetSymbolAddress((void**)&yebuf, g_ye);

    EncodeFn enc = nullptr;
    {
        void* fp = nullptr;
        cudaDriverEntryPointQueryResult qr;
        cudaGetDriverEntryPointByVersion("cuTensorMapEncodeTiled", &fp, 12000,
                                         cudaEnableDefault, &qr);
        enc = (EncodeFn)fp;
    }

    CUtensorMap tmA1, tmB1, tmA2, tmB2;
    enc_map(enc, &tmA1, xd,   Dq, ROWS_TOT, 1);   // [16384,1024] fp16
    enc_map(enc, &tmB1, w1t,  Dq, Fq, Eq);        // [E][4096][1024]
    enc_map(enc, &tmA2, hbuf, Fq, ROWS_TOT, 1);   // [16384,4096]
    enc_map(enc, &tmB2, w2t,  Fq, Dq, Eq);        // [E][1024][4096]

    constexpr int SMEM_SZ = 1024 + 3 * 2 * 16384;  // 99328 -> 2 CTAs/SM
    cudaFuncSetAttribute(gemm_mma<Dq / 64, true, __half, Fq>,
                         cudaFuncAttributeMaxDynamicSharedMemorySize, SMEM_SZ);
    cudaFuncSetAttribute(gemm_mma<Fq / 64, false, float, Dq>,
                         cudaFuncAttributeMaxDynamicSharedMemorySize, SMEM_SZ);

    // 1) gating
    gate_kernel<<<Tq / 4, 128>>>(x, Wg);
    // 2) ordered per-expert scan
    scan_kernel<<<Eq, 1024>>>();
    // 3) gather dispatched tokens (fp16)
    gather_kernel<<<ROWS_TOT, 128>>>(x);
    // 4) weight transposes, exact grids
    {
        dim3 blk(32, 8);
        transpose_k<<<dim3(Fq / 64, Dq / 64, Eq), blk>>>(W1, w1t, Dq, Fq);
        transpose_k<<<dim3(Dq / 64, Fq / 64, Eq), blk>>>(W2, w2t, Fq, Dq);
    }
    // 5) GEMM1: h = gelu(xd @ W1^T + b1)   [16384, 4096] fp16
    gemm_mma<Dq / 64, true, __half, Fq>
        <<<dim3(Fq / 128, ROWS_TOT / 128), 256, SMEM_SZ>>>(tmA1, tmB1, b1, hbuf);
    // 6) GEMM2: ye = h @ W2^T + b2         [16384, 1024] fp32
    gemm_mma<Fq / 64, false, float, Dq>
        <<<dim3(Dq / 128, ROWS_TOT / 128), 256, SMEM_SZ>>>(tmA2, tmB2, b2, yebuf);
    // 7) combine
    combine_kernel<<<Tq, 256>>>(out);
}

// round 12
// speedup vs baseline: 2.2992x; 1.6364x over previous
#include <cuda_runtime.h>
#include <cuda.h>
#include <cuda_fp16.h>
#include <math.h>
#include <stdint.h>

// Problem constants
#define Bq 2
#define Sq 2048
#define Dq 1024
#define Fq 4096
#define Eq 8
#define Tq (Bq * Sq)            // 4096 tokens
#define Cq ((2 * 2 * Tq) / Eq)  // capacity = 2048
#define ROWS_TOT (Eq * Cq)      // 16384

// ---------------- scratch (device globals) --------------------------------
__device__ int    g_idx1[Tq];
__device__ int    g_idx2[Tq];
__device__ int    g_pos1[Tq];
__device__ int    g_pos2[Tq];
__device__ float  g_w1[Tq];
__device__ float  g_w2[Tq];
__device__ int    g_cnt[Eq];                          // occupied slots per expert
__device__ int    g_slot_token[ROWS_TOT];             // slot -> token (-1 empty)
__device__ __half g_xd [(size_t)ROWS_TOT * Dq];       // dispatched tokens fp16  32MB
__device__ __half g_w1t[(size_t)Eq * Fq * Dq];        // W1^T [E][F][D] fp16     64MB
__device__ __half g_w2t[(size_t)Eq * Dq * Fq];        // W2^T [E][D][F] fp16     64MB
__device__ __half g_h  [(size_t)ROWS_TOT * Fq];       // h fp16                 128MB
__device__ float  g_ye [(size_t)ROWS_TOT * Dq];       // ye fp32                 64MB

// ---------------- PTX helpers ----------------------------------------------
__device__ __forceinline__ uint32_t smem_u32(const void* p) {
    uint32_t a;
    asm("{ .reg .u64 t; cvta.to.shared.u64 t, %1; cvt.u32.u64 %0, t; }" : "=r"(a) : "l"(p));
    return a;
}

#define MBAR_INIT(a, c) \
    asm volatile("mbarrier.init.shared.b64 [%0], %1;" :: "r"(a), "r"(c) : "memory")
#define MBAR_EXPECT_TX(a, b) \
    asm volatile("mbarrier.arrive.expect_tx.shared.b64 _, [%0], %1;" :: "r"(a), "r"(b) : "memory")
#define MBAR_ARRIVE(a) \
    asm volatile("mbarrier.arrive.shared.b64 _, [%0];" :: "r"(a) : "memory")
#define FENCE_PROXY_ASYNC() \
    asm volatile("fence.proxy.async.shared::cta;" ::: "memory")

#define MBAR_WAIT(mb, ph) do {                                                  \
    uint32_t _m = (mb); uint32_t _p = (ph);                                     \
    asm volatile("{\n\t.reg .pred P1;\n\t"                                      \
        "WL_%=:\n\t"                                                            \
        "mbarrier.try_wait.parity.acquire.cta.shared::cta.b64 P1, [%0], %1, 0x989680;\n\t" \
        "@P1 bra.uni WD_%=;\n\t"                                                \
        "bra.uni WL_%=;\n\t"                                                    \
        "WD_%=:\n\t}"                                                           \
        :: "r"(_m), "r"(_p) : "memory");                                        \
} while (0)

#define TMA_LD3D(smaddr, tmap, cx, cy, cz, mb)                                  \
    asm volatile("cp.async.bulk.tensor.3d.shared::cta.global.tile.mbarrier::complete_tx::bytes " \
        "[%0], [%1, {%2, %3, %4}], [%5];"                                       \
        :: "r"((uint32_t)(smaddr)), "l"(tmap), "r"((int)(cx)), "r"((int)(cy)),  \
           "r"((int)(cz)), "r"((uint32_t)(mb)) : "memory")

#define LDSM4(r0, r1, r2, r3, addr)                                             \
    asm volatile("ldmatrix.sync.aligned.m8n8.x4.shared.b16 {%0,%1,%2,%3}, [%4];" \
        : "=r"(r0), "=r"(r1), "=r"(r2), "=r"(r3) : "r"(addr))

#define MMA16816(c, a, b0, b1)                                                  \
    asm volatile("mma.sync.aligned.m16n8k16.row.col.f32.f16.f16.f32 "           \
        "{%0,%1,%2,%3}, {%4,%5,%6,%7}, {%8,%9}, {%0,%1,%2,%3};"                 \
        : "+f"((c)[0]), "+f"((c)[1]), "+f"((c)[2]), "+f"((c)[3])                \
        : "r"((a)[0]), "r"((a)[1]), "r"((a)[2]), "r"((a)[3]), "r"(b0), "r"(b1))

// ---------------- kernel 1: gating ----------------------------------------
__global__ void gate_kernel(const float* __restrict__ x,
                            const float* __restrict__ Wg) {
    int t = blockIdx.x * (blockDim.x >> 5) + (threadIdx.x >> 5);
    int lane = threadIdx.x & 31;
    if (t >= Tq) return;

    float acc[Eq];
#pragma unroll
    for (int e = 0; e < Eq; e++) acc[e] = 0.f;
    const float* xr = x + (size_t)t * Dq;
    for (int d = lane; d < Dq; d += 32) {
        float xv = xr[d];
        const float* wr = Wg + (size_t)d * Eq;
#pragma unroll
        for (int e = 0; e < Eq; e++) acc[e] += xv * wr[e];
    }
#pragma unroll
    for (int e = 0; e < Eq; e++)
#pragma unroll
        for (int off = 16; off > 0; off >>= 1)
            acc[e] += __shfl_xor_sync(0xffffffffu, acc[e], off);
    if (lane == 0) {
        int i1 = 0; float l1 = acc[0];
#pragma unroll
        for (int e = 1; e < Eq; e++) if (acc[e] > l1) { l1 = acc[e]; i1 = e; }
        int i2 = -1; float l2 = -3.4e38f;
#pragma unroll
        for (int e = 0; e < Eq; e++) if (e != i1 && acc[e] > l2) { l2 = acc[e]; i2 = e; }
        float s = 0.f, g[Eq];
#pragma unroll
        for (int e = 0; e < Eq; e++) { g[e] = expf(acc[e] - l1); s += g[e]; }
        float g1 = g[i1] / s, g2 = g[i2] / s;
        float denom = g1 + g2 + 1e-9f;
        g_idx1[t] = i1; g_idx2[t] = i2;
        g_w1[t] = g1 / denom; g_w2[t] = g2 / denom;
    }
}

// ---------------- kernel 2: per-expert ordered scan ------------------------
__global__ void scan_kernel() {
    const int e = blockIdx.x;
    const int tid = threadIdx.x;
    const int lane = tid & 31, wid = tid >> 5;
    __shared__ int wsum[32];
    __shared__ int s_total1;

    int* slot = g_slot_token + e * Cq;
    for (int s = tid; s < Cq; s += 1024) slot[s] = -1;
    __syncthreads();

    const int t0 = tid * 4;

    int m1[4], loc1[4], cnt = 0;
#pragma unroll
    for (int i = 0; i < 4; i++) { m1[i] = (g_idx1[t0 + i] == e); loc1[i] = cnt; cnt += m1[i]; }
    int v = cnt;
#pragma unroll
    for (int off = 1; off < 32; off <<= 1) {
        int u = __shfl_up_sync(0xffffffffu, v, off);
        if (lane >= off) v += u;
    }
    if (lane == 31) wsum[wid] = v;
    __syncthreads();
    if (wid == 0) {
        int w = wsum[lane];
#pragma unroll
        for (int off = 1; off < 32; off <<= 1) {
            int u = __shfl_up_sync(0xffffffffu, w, off);
            if (lane >= off) w += u;
        }
        wsum[lane] = w;
    }
    __syncthreads();
    int base = (v - cnt) + (wid ? wsum[wid - 1] : 0);
    if (tid == 0) s_total1 = wsum[31];
    __syncthreads();
#pragma unroll
    for (int i = 0; i < 4; i++) if (m1[i]) {
        int p = base + loc1[i];
        int t = t0 + i;
        if (p < Cq) { g_pos1[t] = p; slot[p] = t; }
        else        { g_pos1[t] = Cq - 1; g_w1[t] = 0.f; }
    }

    int m2[4], loc2[4]; cnt = 0;
#pragma unroll
    for (int i = 0; i < 4; i++) { m2[i] = (g_idx2[t0 + i] == e); loc2[i] = cnt; cnt += m2[i]; }
    v = cnt;
#pragma unroll
    for (int off = 1; off < 32; off <<= 1) {
        int u = __shfl_up_sync(0xffffffffu, v, off);
        if (lane >= off) v += u;
    }
    if (lane == 31) wsum[wid] = v;
    __syncthreads();
    if (wid == 0) {
        int w = wsum[lane];
#pragma unroll
        for (int off = 1; off < 32; off <<= 1) {
            int u = __shfl_up_sync(0xffffffffu, w, off);
            if (lane >= off) w += u;
        }
        wsum[lane] = w;
    }
    __syncthreads();
    int base2 = s_total1 + (v - cnt) + (wid ? wsum[wid - 1] : 0);
#pragma unroll
    for (int i = 0; i < 4; i++) if (m2[i]) {
        int p = base2 + loc2[i];
        int t = t0 + i;
        if (p < Cq) { g_pos2[t] = p; slot[p] = t; }
        else        { g_pos2[t] = Cq - 1; g_w2[t] = 0.f; }
    }

    // occupied slot count for this expert (slots [0, cnt_e) are in use)
    if (tid == 0) {
        int tot = s_total1 + wsum[31];
        g_cnt[e] = tot < Cq ? tot : Cq;
    }
}

// ---------------- kernel 3: gather dispatched tokens -> fp16 ---------------
__global__ void gather_kernel(const float* __restrict__ x) {
    int row = blockIdx.x;               // 0..16383
    int tok = g_slot_token[row];
    __half2* o = (__half2*)(g_xd + (size_t)row * Dq);
    if (tok >= 0) {
        const float4* xi = (const float4*)(x + (size_t)tok * Dq);
        for (int i = threadIdx.x; i < Dq / 4; i += blockDim.x) {
            float4 v = xi[i];
            o[i * 2 + 0] = __floats2half2_rn(v.x, v.y);
            o[i * 2 + 1] = __floats2half2_rn(v.z, v.w);
        }
    } else {
        __half2 z = __floats2half2_rn(0.f, 0.f);
        for (int i = threadIdx.x; i < Dq / 4; i += blockDim.x) {
            o[i * 2 + 0] = z; o[i * 2 + 1] = z;
        }
    }
}

// ---------------- kernel 4: weight transpose fp32 -> fp16 ------------------
__global__ void transpose_k(const float* __restrict__ in, __half* __restrict__ outp,
                            int R, int Cc) {
    __shared__ float t[64][65];
    const int e = blockIdx.z;
    const float* ip = in + (size_t)e * R * Cc;
    __half* op = outp + (size_t)e * R * Cc;
    const int c0 = blockIdx.x * 64, r0 = blockIdx.y * 64;
    const int tx = threadIdx.x, ty = threadIdx.y;   // 32 x 8

#pragma unroll
    for (int j = 0; j < 64; j += 8) {
        t[ty + j][tx]      = ip[(size_t)(r0 + ty + j) * Cc + c0 + tx];
        t[ty + j][tx + 32] = ip[(size_t)(r0 + ty + j) * Cc + c0 + tx + 32];
    }
    __syncthreads();
#pragma unroll
    for (int j = 0; j < 64; j += 8) {
        int cl = ty + j;
        __half2 v = __floats2half2_rn(t[2 * tx][cl], t[2 * tx + 1][cl]);
        *(__half2*)(op + (size_t)(c0 + cl) * R + r0 + 2 * tx) = v;
    }
}

// ---------------- fp16 mma.sync GEMM (128x128x64, round-4 exact) -----------
// 8 warps (2x4 tiling, 64x32 warp tile); control in warp 0, bottom refill.
// NEW: early-exit blocks whose 128 rows are all empty slots (row >= cnt_e).
template <int KT, bool GELU, typename OT, int NTOT>
__global__ void __launch_bounds__(256, 1)
gemm_mma(const __grid_constant__ CUtensorMap tmA,
         const __grid_constant__ CUtensorMap tmB,
         const float* __restrict__ bias, OT* __restrict__ Out) {
    constexpr int S = 3;
    constexpr int TILE_B = 16384;          // 128 rows x 128B (64 fp16)
    extern __shared__ __align__(1024) char smem[];
    const uint32_t sb = smem_u32(smem);
    const int tid = threadIdx.x;
    const int wid = tid >> 5, lane = tid & 31;
    const int row0 = blockIdx.y * 128;
    const int col0 = blockIdx.x * 128;
    const int e = row0 >> 11;              // row0 / 2048

    // skip fully-empty slot blocks (slots are filled as a prefix per expert)
    if ((row0 & (Cq - 1)) >= g_cnt[e]) return;

    const uint32_t FULL0 = sb;             // full[s] = FULL0 + 16*s
    const uint32_t EMPT0 = sb + 8;         // empty[s] = EMPT0 + 16*s
    const uint32_t SA = sb + 1024;
    const uint32_t SB_ = sb + 1024 + S * TILE_B;

    if (tid == 0) {
#pragma unroll
        for (int s = 0; s < S; s++) {
            MBAR_INIT(FULL0 + 16 * s, 1);
            MBAR_INIT(EMPT0 + 16 * s, 8);   // one arrive per warp
        }
        FENCE_PROXY_ASYNC();                // order init before async-proxy TMA
    }
    __syncthreads();

    // warp tiling: 2 (M) x 4 (N); warp tile 64 x 32
    const int warp_m = wid >> 2, warp_n = wid & 3;
    const int m0 = warp_m * 64, n0 = warp_n * 32;
    const uint32_t sw = (uint32_t)(lane & 7) << 4;   // SW128 xor

    uint32_t aoff[4], boff[2];
#pragma unroll
    for (int mi = 0; mi < 4; mi++)
        aoff[mi] = (uint32_t)(m0 + mi * 16 + (lane & 15)) * 128;
#pragma unroll
    for (int p = 0; p < 2; p++)
        boff[p] = (uint32_t)(n0 + (2 * p + ((lane >> 4) & 1)) * 8 + (lane & 7)) * 128;
    const uint32_t kxA = ((lane >> 4) & 1) * 16;
    const uint32_t kxB = ((lane >> 3) & 1) * 16;

    float acc[4][4][4];
#pragma unroll
    for (int mi = 0; mi < 4; mi++)
#pragma unroll
        for (int ni = 0; ni < 4; ni++)
#pragma unroll
            for (int q = 0; q < 4; q++) acc[mi][ni][q] = 0.f;

    if (tid == 0) {
#pragma unroll
        for (int s = 0; s < S && s < KT; s++) {
            MBAR_EXPECT_TX(FULL0 + 16 * s, 2 * TILE_B);
            TMA_LD3D(SA + s * TILE_B, &tmA, s * 64, row0, 0, FULL0 + 16 * s);
            TMA_LD3D(SB_ + s * TILE_B, &tmB, s * 64, col0, e, FULL0 + 16 * s);
        }
    }

#pragma unroll 1
    for (int kt = 0; kt < KT; kt++) {
        const int st = kt % S;
        const int ph = (kt / S) & 1;
        MBAR_WAIT(FULL0 + 16 * st, ph);

        const uint32_t sa = SA + st * TILE_B;
        const uint32_t sbB = SB_ + st * TILE_B;
#pragma unroll
        for (int kk = 0; kk < 4; kk++) {
            const uint32_t ka = ((uint32_t)(kk * 32) + kxA) ^ sw;
            const uint32_t kb = ((uint32_t)(kk * 32) + kxB) ^ sw;
            uint32_t a[4][4], b[4][2];
#pragma unroll
            for (int mi = 0; mi < 4; mi++)
                LDSM4(a[mi][0], a[mi][1], a[mi][2], a[mi][3], sa + aoff[mi] + ka);
#pragma unroll
            for (int p = 0; p < 2; p++) {
                uint32_t r0, r1, r2, r3;
                LDSM4(r0, r1, r2, r3, sbB + boff[p] + kb);
                b[2 * p][0] = r0; b[2 * p][1] = r1;
                b[2 * p + 1][0] = r2; b[2 * p + 1][1] = r3;
            }
#pragma unroll
            for (int mi = 0; mi < 4; mi++)
#pragma unroll
                for (int ni = 0; ni < 4; ni++)
                    MMA16816(acc[mi][ni], a[mi], b[ni][0], b[ni][1]);
        }
        if (lane == 0) MBAR_ARRIVE(EMPT0 + 16 * st);

        if (tid == 0) {
            int j = kt + S;
            if (j < KT) {
                MBAR_WAIT(EMPT0 + 16 * st, ph);
                MBAR_EXPECT_TX(FULL0 + 16 * st, 2 * TILE_B);
                TMA_LD3D(SA + st * TILE_B, &tmA, j * 64, row0, 0, FULL0 + 16 * st);
                TMA_LD3D(SB_ + st * TILE_B, &tmB, j * 64, col0, e, FULL0 + 16 * st);
            }
        }
    }

    // ---------------- epilogue ------------------------------------------
    const float* brow = bias + (size_t)e * NTOT;
#pragma unroll
    for (int mi = 0; mi < 4; mi++) {
#pragma unroll
        for (int ni = 0; ni < 4; ni++) {
            int col = col0 + n0 + ni * 8 + (lane & 3) * 2;
            float bz0 = brow[col], bz1 = brow[col + 1];
#pragma unroll
            for (int h = 0; h < 2; h++) {
                int row = row0 + m0 + mi * 16 + (lane >> 2) + h * 8;
                float v0 = acc[mi][ni][2 * h + 0] + bz0;
                float v1 = acc[mi][ni][2 * h + 1] + bz1;
                if (GELU) {
                    v0 = 0.5f * v0 * (1.f + erff(v0 * 0.70710678118654752f));
                    v1 = 0.5f * v1 * (1.f + erff(v1 * 0.70710678118654752f));
                }
                if (sizeof(OT) == 2) {
                    *(__half2*)((__half*)Out + (size_t)row * NTOT + col) =
                        __floats2half2_rn(v0, v1);
                } else {
                    *(float2*)((float*)Out + (size_t)row * NTOT + col) =
                        make_float2(v0, v1);
                }
            }
        }
    }
}

// ---------------- kernel 7: combine ----------------------------------------
__global__ void combine_kernel(float* __restrict__ out) {
    int t = blockIdx.x;
    int i1 = g_idx1[t], i2 = g_idx2[t];
    float w1 = g_w1[t], w2 = g_w2[t];
    const float4* y1 = (const float4*)(g_ye + ((size_t)i1 * Cq + g_pos1[t]) * Dq);
    const float4* y2 = (const float4*)(g_ye + ((size_t)i2 * Cq + g_pos2[t]) * Dq);
    float4* o = (float4*)(out + (size_t)t * Dq);
    for (int j = threadIdx.x; j < Dq / 4; j += blockDim.x) {
        float4 a = y1[j], b = y2[j];
        float4 r;
        r.x = w1 * a.x + w2 * b.x;
        r.y = w1 * a.y + w2 * b.y;
        r.z = w1 * a.z + w2 * b.z;
        r.w = w1 * a.w + w2 * b.w;
        o[j] = r;
    }
}

// ---------------- host: tensor-map build + launch ---------------------------
typedef CUresult (*EncodeFn)(CUtensorMap*, CUtensorMapDataType, cuuint32_t, void*,
                             const cuuint64_t*, const cuuint64_t*, const cuuint32_t*,
                             const cuuint32_t*, CUtensorMapInterleave, CUtensorMapSwizzle,
                             CUtensorMapL2promotion, CUtensorMapFloatOOBfill);

static void enc_map(EncodeFn fn, CUtensorMap* m, void* p,
                    uint64_t d0, uint64_t d1, uint64_t d2) {
    cuuint64_t dims[3] = {d0, d1, d2};
    cuuint64_t str[2] = {d0 * 2, d0 * d1 * 2};   // fp16
    cuuint32_t box[3] = {64, 128, 1};            // 64 fp16 = 128B rows
    cuuint32_t es[3] = {1, 1, 1};
    fn(m, CU_TENSOR_MAP_DATA_TYPE_FLOAT16, 3, p, dims, str, box, es,
       CU_TENSOR_MAP_INTERLEAVE_NONE, CU_TENSOR_MAP_SWIZZLE_128B,
       CU_TENSOR_MAP_L2_PROMOTION_L2_128B, CU_TENSOR_MAP_FLOAT_OOB_FILL_NONE);
}

extern "C" void kernel_launch(void* const* d_in, const int* in_sizes, int n_in,
                              void* d_out, int out_size) {
    const float* x  = (const float*)d_in[0];
    const float* Wg = (const float*)d_in[1];
    const float* W1 = (const float*)d_in[2];
    const float* b1 = (const float*)d_in[3];
    const float* W2 = (const float*)d_in[4];
    const float* b2 = (const float*)d_in[5];
    float* out = (float*)d_out;

    __half *xd, *w1t, *w2t, *hbuf;
    float* yebuf;
    cudaGetSymbolAddress((void**)&xd,    g_xd);
    cudaGetSymbolAddress((void**)&w1t,   g_w1t);
    cudaGetSymbolAddress((void**)&w2t,   g_w2t);
    cudaGetSymbolAddress((void**)&hbuf,  g_h);
    cudaGetSymbolAddress((void**)&yebuf, g_ye);

    EncodeFn enc = nullptr;
    {
        void* fp = nullptr;
        cudaDriverEntryPointQueryResult qr;
        cudaGetDriverEntryPointByVersion("cuTensorMapEncodeTiled", &fp, 12000,
                                         cudaEnableDefault, &qr);
        enc = (EncodeFn)fp;
    }

    CUtensorMap tmA1, tmB1, tmA2, tmB2;
    enc_map(enc, &tmA1, xd,   Dq, ROWS_TOT, 1);   // [16384,1024] fp16
    enc_map(enc, &tmB1, w1t,  Dq, Fq, Eq);        // [E][4096][1024]
    enc_map(enc, &tmA2, hbuf, Fq, ROWS_TOT, 1);   // [16384,4096]
    enc_map(enc, &tmB2, w2t,  Fq, Dq, Eq);        // [E][1024][4096]

    constexpr int SMEM_SZ = 1024 + 3 * 2 * 16384;  // 99328
    cudaFuncSetAttribute(gemm_mma<Dq / 64, true, __half, Fq>,
                         cudaFuncAttributeMaxDynamicSharedMemorySize, SMEM_SZ);
    cudaFuncSetAttribute(gemm_mma<Fq / 64, false, float, Dq>,
                         cudaFuncAttributeMaxDynamicSharedMemorySize, SMEM_SZ);

    // 1) gating
    gate_kernel<<<Tq / 4, 128>>>(x, Wg);
    // 2) ordered per-expert scan (also writes g_cnt)
    scan_kernel<<<Eq, 1024>>>();
    // 3) gather dispatched tokens (fp16)
    gather_kernel<<<ROWS_TOT, 128>>>(x);
    // 4) weight transposes, exact grids
    {
        dim3 blk(32, 8);
        transpose_k<<<dim3(Fq / 64, Dq / 64, Eq), blk>>>(W1, w1t, Dq, Fq);
        transpose_k<<<dim3(Dq / 64, Fq / 64, Eq), blk>>>(W2, w2t, Fq, Dq);
    }
    // 5) GEMM1: h = gelu(xd @ W1^T + b1)   [16384, 4096] fp16 (empty blocks skipped)
    gemm_mma<Dq / 64, true, __half, Fq>
        <<<dim3(Fq / 128, ROWS_TOT / 128), 256, SMEM_SZ>>>(tmA1, tmB1, b1, hbuf);
    // 6) GEMM2: ye = h @ W2^T + b2         [16384, 1024] fp32 (empty blocks skipped)
    gemm_mma<Fq / 64, false, float, Dq>
        <<<dim3(Dq / 128, ROWS_TOT / 128), 256, SMEM_SZ>>>(tmA2, tmB2, b2, yebuf);
    // 7) combine
    combine_kernel<<<Tq, 256>>>(out);
}

// round 14
// speedup vs baseline: 2.3117x; 1.0055x over previous
#include <cuda_runtime.h>
#include <cuda.h>
#include <cuda_fp16.h>
#include <math.h>
#include <stdint.h>

// Problem constants
#define Bq 2
#define Sq 2048
#define Dq 1024
#define Fq 4096
#define Eq 8
#define Tq (Bq * Sq)            // 4096 tokens
#define Cq ((2 * 2 * Tq) / Eq)  // capacity = 2048
#define ROWS_TOT (Eq * Cq)      // 16384

// ---------------- scratch (device globals) --------------------------------
__device__ int    g_idx1[Tq];
__device__ int    g_idx2[Tq];
__device__ int    g_pos1[Tq];
__device__ int    g_pos2[Tq];
__device__ float  g_w1[Tq];
__device__ float  g_w2[Tq];
__device__ int    g_cnt[Eq];                          // occupied slots per expert
__device__ int    g_slot_token[ROWS_TOT];             // slot -> token (-1 empty)
__device__ __half g_xd [(size_t)ROWS_TOT * Dq];       // dispatched tokens fp16  32MB
__device__ __half g_w1t[(size_t)Eq * Fq * Dq];        // W1^T [E][F][D] fp16     64MB
__device__ __half g_w2t[(size_t)Eq * Dq * Fq];        // W2^T [E][D][F] fp16     64MB
__device__ __half g_h  [(size_t)ROWS_TOT * Fq];       // h fp16                 128MB
__device__ float  g_ye [(size_t)ROWS_TOT * Dq];       // ye fp32                 64MB

// ---------------- PTX helpers ----------------------------------------------
__device__ __forceinline__ uint32_t smem_u32(const void* p) {
    uint32_t a;
    asm("{ .reg .u64 t; cvta.to.shared.u64 t, %1; cvt.u32.u64 %0, t; }" : "=r"(a) : "l"(p));
    return a;
}

#define MBAR_INIT(a, c) \
    asm volatile("mbarrier.init.shared.b64 [%0], %1;" :: "r"(a), "r"(c) : "memory")
#define MBAR_EXPECT_TX(a, b) \
    asm volatile("mbarrier.arrive.expect_tx.shared.b64 _, [%0], %1;" :: "r"(a), "r"(b) : "memory")
#define MBAR_ARRIVE(a) \
    asm volatile("mbarrier.arrive.shared.b64 _, [%0];" :: "r"(a) : "memory")
#define FENCE_PROXY_ASYNC() \
    asm volatile("fence.proxy.async.shared::cta;" ::: "memory")

#define MBAR_WAIT(mb, ph) do {                                                  \
    uint32_t _m = (mb); uint32_t _p = (ph);                                     \
    asm volatile("{\n\t.reg .pred P1;\n\t"                                      \
        "WL_%=:\n\t"                                                            \
        "mbarrier.try_wait.parity.acquire.cta.shared::cta.b64 P1, [%0], %1, 0x989680;\n\t" \
        "@P1 bra.uni WD_%=;\n\t"                                                \
        "bra.uni WL_%=;\n\t"                                                    \
        "WD_%=:\n\t}"                                                           \
        :: "r"(_m), "r"(_p) : "memory");                                        \
} while (0)

#define TMA_LD3D(smaddr, tmap, cx, cy, cz, mb)                                  \
    asm volatile("cp.async.bulk.tensor.3d.shared::cta.global.tile.mbarrier::complete_tx::bytes " \
        "[%0], [%1, {%2, %3, %4}], [%5];"                                       \
        :: "r"((uint32_t)(smaddr)), "l"(tmap), "r"((int)(cx)), "r"((int)(cy)),  \
           "r"((int)(cz)), "r"((uint32_t)(mb)) : "memory")

#define LDSM4(r0, r1, r2, r3, addr)                                             \
    asm volatile("ldmatrix.sync.aligned.m8n8.x4.shared.b16 {%0,%1,%2,%3}, [%4];" \
        : "=r"(r0), "=r"(r1), "=r"(r2), "=r"(r3) : "r"(addr))

#define MMA16816(c, a, b0, b1)                                                  \
    asm volatile("mma.sync.aligned.m16n8k16.row.col.f32.f16.f16.f32 "           \
        "{%0,%1,%2,%3}, {%4,%5,%6,%7}, {%8,%9}, {%0,%1,%2,%3};"                 \
        : "+f"((c)[0]), "+f"((c)[1]), "+f"((c)[2]), "+f"((c)[3])                \
        : "r"((a)[0]), "r"((a)[1]), "r"((a)[2]), "r"((a)[3]), "r"(b0), "r"(b1))

// ---------------- kernel 1: gating ----------------------------------------
__global__ void gate_kernel(const float* __restrict__ x,
                            const float* __restrict__ Wg) {
    int t = blockIdx.x * (blockDim.x >> 5) + (threadIdx.x >> 5);
    int lane = threadIdx.x & 31;
    if (t >= Tq) return;

    float acc[Eq];
#pragma unroll
    for (int e = 0; e < Eq; e++) acc[e] = 0.f;
    const float* xr = x + (size_t)t * Dq;
    for (int d = lane; d < Dq; d += 32) {
        float xv = xr[d];
        const float* wr = Wg + (size_t)d * Eq;
#pragma unroll
        for (int e = 0; e < Eq; e++) acc[e] += xv * wr[e];
    }
#pragma unroll
    for (int e = 0; e < Eq; e++)
#pragma unroll
        for (int off = 16; off > 0; off >>= 1)
            acc[e] += __shfl_xor_sync(0xffffffffu, acc[e], off);
    if (lane == 0) {
        int i1 = 0; float l1 = acc[0];
#pragma unroll
        for (int e = 1; e < Eq; e++) if (acc[e] > l1) { l1 = acc[e]; i1 = e; }
        int i2 = -1; float l2 = -3.4e38f;
#pragma unroll
        for (int e = 0; e < Eq; e++) if (e != i1 && acc[e] > l2) { l2 = acc[e]; i2 = e; }
        float s = 0.f, g[Eq];
#pragma unroll
        for (int e = 0; e < Eq; e++) { g[e] = expf(acc[e] - l1); s += g[e]; }
        float g1 = g[i1] / s, g2 = g[i2] / s;
        float denom = g1 + g2 + 1e-9f;
        g_idx1[t] = i1; g_idx2[t] = i2;
        g_w1[t] = g1 / denom; g_w2[t] = g2 / denom;
    }
}

// ---------------- kernel 2: per-expert ordered scan ------------------------
__global__ void scan_kernel() {
    const int e = blockIdx.x;
    const int tid = threadIdx.x;
    const int lane = tid & 31, wid = tid >> 5;
    __shared__ int wsum[32];
    __shared__ int s_total1;

    int* slot = g_slot_token + e * Cq;
    for (int s = tid; s < Cq; s += 1024) slot[s] = -1;
    __syncthreads();

    const int t0 = tid * 4;

    int m1[4], loc1[4], cnt = 0;
#pragma unroll
    for (int i = 0; i < 4; i++) { m1[i] = (g_idx1[t0 + i] == e); loc1[i] = cnt; cnt += m1[i]; }
    int v = cnt;
#pragma unroll
    for (int off = 1; off < 32; off <<= 1) {
        int u = __shfl_up_sync(0xffffffffu, v, off);
        if (lane >= off) v += u;
    }
    if (lane == 31) wsum[wid] = v;
    __syncthreads();
    if (wid == 0) {
        int w = wsum[lane];
#pragma unroll
        for (int off = 1; off < 32; off <<= 1) {
            int u = __shfl_up_sync(0xffffffffu, w, off);
            if (lane >= off) w += u;
        }
        wsum[lane] = w;
    }
    __syncthreads();
    int base = (v - cnt) + (wid ? wsum[wid - 1] : 0);
    if (tid == 0) s_total1 = wsum[31];
    __syncthreads();
#pragma unroll
    for (int i = 0; i < 4; i++) if (m1[i]) {
        int p = base + loc1[i];
        int t = t0 + i;
        if (p < Cq) { g_pos1[t] = p; slot[p] = t; }
        else        { g_pos1[t] = Cq - 1; g_w1[t] = 0.f; }
    }

    int m2[4], loc2[4]; cnt = 0;
#pragma unroll
    for (int i = 0; i < 4; i++) { m2[i] = (g_idx2[t0 + i] == e); loc2[i] = cnt; cnt += m2[i]; }
    v = cnt;
#pragma unroll
    for (int off = 1; off < 32; off <<= 1) {
        int u = __shfl_up_sync(0xffffffffu, v, off);
        if (lane >= off) v += u;
    }
    if (lane == 31) wsum[wid] = v;
    __syncthreads();
    if (wid == 0) {
        int w = wsum[lane];
#pragma unroll
        for (int off = 1; off < 32; off <<= 1) {
            int u = __shfl_up_sync(0xffffffffu, w, off);
            if (lane >= off) w += u;
        }
        wsum[lane] = w;
    }
    __syncthreads();
    int base2 = s_total1 + (v - cnt) + (wid ? wsum[wid - 1] : 0);
#pragma unroll
    for (int i = 0; i < 4; i++) if (m2[i]) {
        int p = base2 + loc2[i];
        int t = t0 + i;
        if (p < Cq) { g_pos2[t] = p; slot[p] = t; }
        else        { g_pos2[t] = Cq - 1; g_w2[t] = 0.f; }
    }

    // occupied slot count for this expert (slots [0, cnt_e) are in use)
    if (tid == 0) {
        int tot = s_total1 + wsum[31];
        g_cnt[e] = tot < Cq ? tot : Cq;
    }
}

// ---------------- kernel 3: gather dispatched tokens -> fp16 ---------------
// zero-fill only up to the 128-padded per-expert boundary; rows beyond it are
// never read (their GEMM blocks early-return) and g_ye there stays zero-init.
__global__ void gather_kernel(const float* __restrict__ x) {
    int row = blockIdx.x;               // 0..16383
    int tok = g_slot_token[row];
    __half2* o = (__half2*)(g_xd + (size_t)row * Dq);
    if (tok >= 0) {
        const float4* xi = (const float4*)(x + (size_t)tok * Dq);
        for (int i = threadIdx.x; i < Dq / 4; i += blockDim.x) {
            float4 v = xi[i];
            o[i * 2 + 0] = __floats2half2_rn(v.x, v.y);
            o[i * 2 + 1] = __floats2half2_rn(v.z, v.w);
        }
    } else {
        int e = row >> 11;
        int slotpos = row & (Cq - 1);
        int padded = (g_cnt[e] + 127) & ~127;
        if (slotpos >= padded) return;   // never read by GEMM1
        __half2 z = __floats2half2_rn(0.f, 0.f);
        for (int i = threadIdx.x; i < Dq / 4; i += blockDim.x) {
            o[i * 2 + 0] = z; o[i * 2 + 1] = z;
        }
    }
}

// ---------------- kernel 4: weight transpose fp32 -> fp16 ------------------
__global__ void transpose_k(const float* __restrict__ in, __half* __restrict__ outp,
                            int R, int Cc) {
    __shared__ float t[64][65];
    const int e = blockIdx.z;
    const float* ip = in + (size_t)e * R * Cc;
    __half* op = outp + (size_t)e * R * Cc;
    const int c0 = blockIdx.x * 64, r0 = blockIdx.y * 64;
    const int tx = threadIdx.x, ty = threadIdx.y;   // 32 x 8

#pragma unroll
    for (int j = 0; j < 64; j += 8) {
        t[ty + j][tx]      = ip[(size_t)(r0 + ty + j) * Cc + c0 + tx];
        t[ty + j][tx + 32] = ip[(size_t)(r0 + ty + j) * Cc + c0 + tx + 32];
    }
    __syncthreads();
#pragma unroll
    for (int j = 0; j < 64; j += 8) {
        int cl = ty + j;
        __half2 v = __floats2half2_rn(t[2 * tx][cl], t[2 * tx + 1][cl]);
        *(__half2*)(op + (size_t)(c0 + cl) * R + r0 + 2 * tx) = v;
    }
}

// ---------------- fp16 mma.sync GEMM (128x128x64, round-12 exact) ----------
// 8 warps (2x4 tiling, 64x32 warp tile); control in warp 0, bottom refill.
// Empty slot blocks (row >= cnt_e) early-return.
template <int KT, bool GELU, typename OT, int NTOT>
__global__ void __launch_bounds__(256, 1)
gemm_mma(const __grid_constant__ CUtensorMap tmA,
         const __grid_constant__ CUtensorMap tmB,
         const float* __restrict__ bias, OT* __restrict__ Out) {
    constexpr int S = 3;
    constexpr int TILE_B = 16384;          // 128 rows x 128B (64 fp16)
    extern __shared__ __align__(1024) char smem[];
    const uint32_t sb = smem_u32(smem);
    const int tid = threadIdx.x;
    const int wid = tid >> 5, lane = tid & 31;
    const int row0 = blockIdx.y * 128;
    const int col0 = blockIdx.x * 128;
    const int e = row0 >> 11;              // row0 / 2048

    // skip fully-empty slot blocks (slots are filled as a prefix per expert)
    if ((row0 & (Cq - 1)) >= g_cnt[e]) return;

    const uint32_t FULL0 = sb;             // full[s] = FULL0 + 16*s
    const uint32_t EMPT0 = sb + 8;         // empty[s] = EMPT0 + 16*s
    const uint32_t SA = sb + 1024;
    const uint32_t SB_ = sb + 1024 + S * TILE_B;

    if (tid == 0) {
#pragma unroll
        for (int s = 0; s < S; s++) {
            MBAR_INIT(FULL0 + 16 * s, 1);
            MBAR_INIT(EMPT0 + 16 * s, 8);   // one arrive per warp
        }
        FENCE_PROXY_ASYNC();                // order init before async-proxy TMA
    }
    __syncthreads();

    // warp tiling: 2 (M) x 4 (N); warp tile 64 x 32
    const int warp_m = wid >> 2, warp_n = wid & 3;
    const int m0 = warp_m * 64, n0 = warp_n * 32;
    const uint32_t sw = (uint32_t)(lane & 7) << 4;   // SW128 xor

    uint32_t aoff[4], boff[2];
#pragma unroll
    for (int mi = 0; mi < 4; mi++)
        aoff[mi] = (uint32_t)(m0 + mi * 16 + (lane & 15)) * 128;
#pragma unroll
    for (int p = 0; p < 2; p++)
        boff[p] = (uint32_t)(n0 + (2 * p + ((lane >> 4) & 1)) * 8 + (lane & 7)) * 128;
    const uint32_t kxA = ((lane >> 4) & 1) * 16;
    const uint32_t kxB = ((lane >> 3) & 1) * 16;

    float acc[4][4][4];
#pragma unroll
    for (int mi = 0; mi < 4; mi++)
#pragma unroll
        for (int ni = 0; ni < 4; ni++)
#pragma unroll
            for (int q = 0; q < 4; q++) acc[mi][ni][q] = 0.f;

    if (tid == 0) {
#pragma unroll
        for (int s = 0; s < S && s < KT; s++) {
            MBAR_EXPECT_TX(FULL0 + 16 * s, 2 * TILE_B);
            TMA_LD3D(SA + s * TILE_B, &tmA, s * 64, row0, 0, FULL0 + 16 * s);
            TMA_LD3D(SB_ + s * TILE_B, &tmB, s * 64, col0, e, FULL0 + 16 * s);
        }
    }

#pragma unroll 1
    for (int kt = 0; kt < KT; kt++) {
        const int st = kt % S;
        const int ph = (kt / S) & 1;
        MBAR_WAIT(FULL0 + 16 * st, ph);

        const uint32_t sa = SA + st * TILE_B;
        const uint32_t sbB = SB_ + st * TILE_B;
#pragma unroll
        for (int kk = 0; kk < 4; kk++) {
            const uint32_t ka = ((uint32_t)(kk * 32) + kxA) ^ sw;
            const uint32_t kb = ((uint32_t)(kk * 32) + kxB) ^ sw;
            uint32_t a[4][4], b[4][2];
#pragma unroll
            for (int mi = 0; mi < 4; mi++)
                LDSM4(a[mi][0], a[mi][1], a[mi][2], a[mi][3], sa + aoff[mi] + ka);
#pragma unroll
            for (int p = 0; p < 2; p++) {
                uint32_t r0, r1, r2, r3;
                LDSM4(r0, r1, r2, r3, sbB + boff[p] + kb);
                b[2 * p][0] = r0; b[2 * p][1] = r1;
                b[2 * p + 1][0] = r2; b[2 * p + 1][1] = r3;
            }
#pragma unroll
            for (int mi = 0; mi < 4; mi++)
#pragma unroll
                for (int ni = 0; ni < 4; ni++)
                    MMA16816(acc[mi][ni], a[mi], b[ni][0], b[ni][1]);
        }
        if (lane == 0) MBAR_ARRIVE(EMPT0 + 16 * st);

        if (tid == 0) {
            int j = kt + S;
            if (j < KT) {
                MBAR_WAIT(EMPT0 + 16 * st, ph);
                MBAR_EXPECT_TX(FULL0 + 16 * st, 2 * TILE_B);
                TMA_LD3D(SA + st * TILE_B, &tmA, j * 64, row0, 0, FULL0 + 16 * st);
                TMA_LD3D(SB_ + st * TILE_B, &tmB, j * 64, col0, e, FULL0 + 16 * st);
            }
        }
    }

    // ---------------- epilogue ------------------------------------------
    const float* brow = bias + (size_t)e * NTOT;
#pragma unroll
    for (int mi = 0; mi < 4; mi++) {
#pragma unroll
        for (int ni = 0; ni < 4; ni++) {
            int col = col0 + n0 + ni * 8 + (lane & 3) * 2;
            float bz0 = brow[col], bz1 = brow[col + 1];
#pragma unroll
            for (int h = 0; h < 2; h++) {
                int row = row0 + m0 + mi * 16 + (lane >> 2) + h * 8;
                float v0 = acc[mi][ni][2 * h + 0] + bz0;
                float v1 = acc[mi][ni][2 * h + 1] + bz1;
                if (GELU) {
                    v0 = 0.5f * v0 * (1.f + erff(v0 * 0.70710678118654752f));
                    v1 = 0.5f * v1 * (1.f + erff(v1 * 0.70710678118654752f));
                }
                if (sizeof(OT) == 2) {
                    *(__half2*)((__half*)Out + (size_t)row * NTOT + col) =
                        __floats2half2_rn(v0, v1);
                } else {
                    *(float2*)((float*)Out + (size_t)row * NTOT + col) =
                        make_float2(v0, v1);
                }
            }
        }
    }
}

// ---------------- kernel 7: combine (128 thr, 2 float4/thread, MLP=4) ------
__global__ void combine_kernel(float* __restrict__ out) {
    int t = blockIdx.x;
    int i1 = g_idx1[t], i2 = g_idx2[t];
    float w1 = g_w1[t], w2 = g_w2[t];
    const float4* y1 = (const float4*)(g_ye + ((size_t)i1 * Cq + g_pos1[t]) * Dq);
    const float4* y2 = (const float4*)(g_ye + ((size_t)i2 * Cq + g_pos2[t]) * Dq);
    float4* o = (float4*)(out + (size_t)t * Dq);
    int j0 = threadIdx.x;
    int j1 = threadIdx.x + 128;
    float4 a0 = __ldg(y1 + j0), b0 = __ldg(y2 + j0);
    float4 a1 = __ldg(y1 + j1), b1 = __ldg(y2 + j1);
    float4 r0, r1;
    r0.x = w1 * a0.x + w2 * b0.x;  r0.y = w1 * a0.y + w2 * b0.y;
    r0.z = w1 * a0.z + w2 * b0.z;  r0.w = w1 * a0.w + w2 * b0.w;
    r1.x = w1 * a1.x + w2 * b1.x;  r1.y = w1 * a1.y + w2 * b1.y;
    r1.z = w1 * a1.z + w2 * b1.z;  r1.w = w1 * a1.w + w2 * b1.w;
    o[j0] = r0;
    o[j1] = r1;
}

// ---------------- host: tensor-map build + launch ---------------------------
typedef CUresult (*EncodeFn)(CUtensorMap*, CUtensorMapDataType, cuuint32_t, void*,
                             const cuuint64_t*, const cuuint64_t*, const cuuint32_t*,
                             const cuuint32_t*, CUtensorMapInterleave, CUtensorMapSwizzle,
                             CUtensorMapL2promotion, CUtensorMapFloatOOBfill);

static void enc_map(EncodeFn fn, CUtensorMap* m, void* p,
                    uint64_t d0, uint64_t d1, uint64_t d2) {
    cuuint64_t dims[3] = {d0, d1, d2};
    cuuint64_t str[2] = {d0 * 2, d0 * d1 * 2};   // fp16
    cuuint32_t box[3] = {64, 128, 1};            // 64 fp16 = 128B rows
    cuuint32_t es[3] = {1, 1, 1};
    fn(m, CU_TENSOR_MAP_DATA_TYPE_FLOAT16, 3, p, dims, str, box, es,
       CU_TENSOR_MAP_INTERLEAVE_NONE, CU_TENSOR_MAP_SWIZZLE_128B,
       CU_TENSOR_MAP_L2_PROMOTION_L2_128B, CU_TENSOR_MAP_FLOAT_OOB_FILL_NONE);
}

extern "C" void kernel_launch(void* const* d_in, const int* in_sizes, int n_in,
                              void* d_out, int out_size) {
    const float* x  = (const float*)d_in[0];
    const float* Wg = (const float*)d_in[1];
    const float* W1 = (const float*)d_in[2];
    const float* b1 = (const float*)d_in[3];
    const float* W2 = (const float*)d_in[4];
    const float* b2 = (const float*)d_in[5];
    float* out = (float*)d_out;

    __half *xd, *w1t, *w2t, *hbuf;
    float* yebuf;
    cudaGetSymbolAddress((void**)&xd,    g_xd);
    cudaGetSymbolAddress((void**)&w1t,   g_w1t);
    cudaGetSymbolAddress((void**)&w2t,   g_w2t);
    cudaGetSymbolAddress((void**)&hbuf,  g_h);
    cudaGetSymbolAddress((void**)&yebuf, g_ye);

    EncodeFn enc = nullptr;
    {
        void* fp = nullptr;
        cudaDriverEntryPointQueryResult qr;
        cudaGetDriverEntryPointByVersion("cuTensorMapEncodeTiled", &fp, 12000,
                                         cudaEnableDefault, &qr);
        enc = (EncodeFn)fp;
    }

    CUtensorMap tmA1, tmB1, tmA2, tmB2;
    enc_map(enc, &tmA1, xd,   Dq, ROWS_TOT, 1);   // [16384,1024] fp16
    enc_map(enc, &tmB1, w1t,  Dq, Fq, Eq);        // [E][4096][1024]
    enc_map(enc, &tmA2, hbuf, Fq, ROWS_TOT, 1);   // [16384,4096]
    enc_map(enc, &tmB2, w2t,  Fq, Dq, Eq);        // [E][1024][4096]

    constexpr int SMEM_SZ = 1024 + 3 * 2 * 16384;  // 99328
    cudaFuncSetAttribute(gemm_mma<Dq / 64, true, __half, Fq>,
                         cudaFuncAttributeMaxDynamicSharedMemorySize, SMEM_SZ);
    cudaFuncSetAttribute(gemm_mma<Fq / 64, false, float, Dq>,
                         cudaFuncAttributeMaxDynamicSharedMemorySize, SMEM_SZ);

    // 1) gating
    gate_kernel<<<Tq / 4, 128>>>(x, Wg);
    // 2) ordered per-expert scan (also writes g_cnt)
    scan_kernel<<<Eq, 1024>>>();
    // 3) gather dispatched tokens (fp16; zero-fill trimmed to padded boundary)
    gather_kernel<<<ROWS_TOT, 128>>>(x);
    // 4) weight transposes, exact grids
    {
        dim3 blk(32, 8);
        transpose_k<<<dim3(Fq / 64, Dq / 64, Eq), blk>>>(W1, w1t, Dq, Fq);
        transpose_k<<<dim3(Dq / 64, Fq / 64, Eq), blk>>>(W2, w2t, Fq, Dq);
    }
    // 5) GEMM1: h = gelu(xd @ W1^T + b1)   [16384, 4096] fp16 (empty blocks skipped)
    gemm_mma<Dq / 64, true, __half, Fq>
        <<<dim3(Fq / 128, ROWS_TOT / 128), 256, SMEM_SZ>>>(tmA1, tmB1, b1, hbuf);
    // 6) GEMM2: ye = h @ W2^T + b2         [16384, 1024] fp32 (empty blocks skipped)
    gemm_mma<Fq / 64, false, float, Dq>
        <<<dim3(Dq / 128, ROWS_TOT / 128), 256, SMEM_SZ>>>(tmA2, tmB2, b2, yebuf);
    // 7) combine
    combine_kernel<<<Tq, 128>>>(out);
}

// round 16
// speedup vs baseline: 2.3120x; 1.0001x over previous
#include <cuda_runtime.h>
#include <cuda.h>
#include <cuda_fp16.h>
#include <math.h>
#include <stdint.h>

// Problem constants
#define Bq 2
#define Sq 2048
#define Dq 1024
#define Fq 4096
#define Eq 8
#define Tq (Bq * Sq)            // 4096 tokens
#define Cq ((2 * 2 * Tq) / Eq)  // capacity = 2048
#define ROWS_TOT (Eq * Cq)      // 16384

// ---------------- scratch (device globals) --------------------------------
__device__ int    g_idx1[Tq];
__device__ int    g_idx2[Tq];
__device__ int    g_pos1[Tq];
__device__ int    g_pos2[Tq];
__device__ float  g_w1[Tq];
__device__ float  g_w2[Tq];
__device__ int    g_cnt[Eq];                          // occupied slots per expert
__device__ int    g_slot_token[ROWS_TOT];             // slot -> token (-1 empty)
__device__ __half g_xd [(size_t)ROWS_TOT * Dq];       // dispatched tokens fp16  32MB
__device__ __half g_w1t[(size_t)Eq * Fq * Dq];        // W1^T [E][F][D] fp16     64MB
__device__ __half g_w2t[(size_t)Eq * Dq * Fq];        // W2^T [E][D][F] fp16     64MB
__device__ __half g_h  [(size_t)ROWS_TOT * Fq];       // h fp16                 128MB
__device__ float  g_ye [(size_t)ROWS_TOT * Dq];       // ye fp32                 64MB

// ---------------- PTX helpers ----------------------------------------------
__device__ __forceinline__ uint32_t smem_u32(const void* p) {
    uint32_t a;
    asm("{ .reg .u64 t; cvta.to.shared.u64 t, %1; cvt.u32.u64 %0, t; }" : "=r"(a) : "l"(p));
    return a;
}

#define MBAR_INIT(a, c) \
    asm volatile("mbarrier.init.shared.b64 [%0], %1;" :: "r"(a), "r"(c) : "memory")
#define MBAR_EXPECT_TX(a, b) \
    asm volatile("mbarrier.arrive.expect_tx.shared.b64 _, [%0], %1;" :: "r"(a), "r"(b) : "memory")
#define MBAR_ARRIVE(a) \
    asm volatile("mbarrier.arrive.shared.b64 _, [%0];" :: "r"(a) : "memory")
#define FENCE_PROXY_ASYNC() \
    asm volatile("fence.proxy.async.shared::cta;" ::: "memory")

#define MBAR_WAIT(mb, ph) do {                                                  \
    uint32_t _m = (mb); uint32_t _p = (ph);                                     \
    asm volatile("{\n\t.reg .pred P1;\n\t"                                      \
        "WL_%=:\n\t"                                                            \
        "mbarrier.try_wait.parity.acquire.cta.shared::cta.b64 P1, [%0], %1, 0x989680;\n\t" \
        "@P1 bra.uni WD_%=;\n\t"                                                \
        "bra.uni WL_%=;\n\t"                                                    \
        "WD_%=:\n\t}"                                                           \
        :: "r"(_m), "r"(_p) : "memory");                                        \
} while (0)

#define TMA_LD3D(smaddr, tmap, cx, cy, cz, mb)                                  \
    asm volatile("cp.async.bulk.tensor.3d.shared::cta.global.tile.mbarrier::complete_tx::bytes " \
        "[%0], [%1, {%2, %3, %4}], [%5];"                                       \
        :: "r"((uint32_t)(smaddr)), "l"(tmap), "r"((int)(cx)), "r"((int)(cy)),  \
           "r"((int)(cz)), "r"((uint32_t)(mb)) : "memory")

#define LDSM4(r0, r1, r2, r3, addr)                                             \
    asm volatile("ldmatrix.sync.aligned.m8n8.x4.shared.b16 {%0,%1,%2,%3}, [%4];" \
        : "=r"(r0), "=r"(r1), "=r"(r2), "=r"(r3) : "r"(addr))

#define MMA16816(c, a, b0, b1)                                                  \
    asm volatile("mma.sync.aligned.m16n8k16.row.col.f32.f16.f16.f32 "           \
        "{%0,%1,%2,%3}, {%4,%5,%6,%7}, {%8,%9}, {%0,%1,%2,%3};"                 \
        : "+f"((c)[0]), "+f"((c)[1]), "+f"((c)[2]), "+f"((c)[3])                \
        : "r"((a)[0]), "r"((a)[1]), "r"((a)[2]), "r"((a)[3]), "r"(b0), "r"(b1))

// ---------------- kernel 1: gating ----------------------------------------
__global__ void gate_kernel(const float* __restrict__ x,
                            const float* __restrict__ Wg) {
    int t = blockIdx.x * (blockDim.x >> 5) + (threadIdx.x >> 5);
    int lane = threadIdx.x & 31;
    if (t >= Tq) return;

    float acc[Eq];
#pragma unroll
    for (int e = 0; e < Eq; e++) acc[e] = 0.f;
    const float* xr = x + (size_t)t * Dq;
    for (int d = lane; d < Dq; d += 32) {
        float xv = xr[d];
        const float* wr = Wg + (size_t)d * Eq;
#pragma unroll
        for (int e = 0; e < Eq; e++) acc[e] += xv * wr[e];
    }
#pragma unroll
    for (int e = 0; e < Eq; e++)
#pragma unroll
        for (int off = 16; off > 0; off >>= 1)
            acc[e] += __shfl_xor_sync(0xffffffffu, acc[e], off);
    if (lane == 0) {
        int i1 = 0; float l1 = acc[0];
#pragma unroll
        for (int e = 1; e < Eq; e++) if (acc[e] > l1) { l1 = acc[e]; i1 = e; }
        int i2 = -1; float l2 = -3.4e38f;
#pragma unroll
        for (int e = 0; e < Eq; e++) if (e != i1 && acc[e] > l2) { l2 = acc[e]; i2 = e; }
        float s = 0.f, g[Eq];
#pragma unroll
        for (int e = 0; e < Eq; e++) { g[e] = expf(acc[e] - l1); s += g[e]; }
        float g1 = g[i1] / s, g2 = g[i2] / s;
        float denom = g1 + g2 + 1e-9f;
        g_idx1[t] = i1; g_idx2[t] = i2;
        g_w1[t] = g1 / denom; g_w2[t] = g2 / denom;
    }
}

// ---------------- kernel 2: per-expert ordered scan ------------------------
__global__ void scan_kernel() {
    const int e = blockIdx.x;
    const int tid = threadIdx.x;
    const int lane = tid & 31, wid = tid >> 5;
    __shared__ int wsum[32];
    __shared__ int s_total1;

    int* slot = g_slot_token + e * Cq;
    for (int s = tid; s < Cq; s += 1024) slot[s] = -1;
    __syncthreads();

    const int t0 = tid * 4;

    int m1[4], loc1[4], cnt = 0;
#pragma unroll
    for (int i = 0; i < 4; i++) { m1[i] = (g_idx1[t0 + i] == e); loc1[i] = cnt; cnt += m1[i]; }
    int v = cnt;
#pragma unroll
    for (int off = 1; off < 32; off <<= 1) {
        int u = __shfl_up_sync(0xffffffffu, v, off);
        if (lane >= off) v += u;
    }
    if (lane == 31) wsum[wid] = v;
    __syncthreads();
    if (wid == 0) {
        int w = wsum[lane];
#pragma unroll
        for (int off = 1; off < 32; off <<= 1) {
            int u = __shfl_up_sync(0xffffffffu, w, off);
            if (lane >= off) w += u;
        }
        wsum[lane] = w;
    }
    __syncthreads();
    int base = (v - cnt) + (wid ? wsum[wid - 1] : 0);
    if (tid == 0) s_total1 = wsum[31];
    __syncthreads();
#pragma unroll
    for (int i = 0; i < 4; i++) if (m1[i]) {
        int p = base + loc1[i];
        int t = t0 + i;
        if (p < Cq) { g_pos1[t] = p; slot[p] = t; }
        else        { g_pos1[t] = Cq - 1; g_w1[t] = 0.f; }
    }

    int m2[4], loc2[4]; cnt = 0;
#pragma unroll
    for (int i = 0; i < 4; i++) { m2[i] = (g_idx2[t0 + i] == e); loc2[i] = cnt; cnt += m2[i]; }
    v = cnt;
#pragma unroll
    for (int off = 1; off < 32; off <<= 1) {
        int u = __shfl_up_sync(0xffffffffu, v, off);
        if (lane >= off) v += u;
    }
    if (lane == 31) wsum[wid] = v;
    __syncthreads();
    if (wid == 0) {
        int w = wsum[lane];
#pragma unroll
        for (int off = 1; off < 32; off <<= 1) {
            int u = __shfl_up_sync(0xffffffffu, w, off);
            if (lane >= off) w += u;
        }
        wsum[lane] = w;
    }
    __syncthreads();
    int base2 = s_total1 + (v - cnt) + (wid ? wsum[wid - 1] : 0);
#pragma unroll
    for (int i = 0; i < 4; i++) if (m2[i]) {
        int p = base2 + loc2[i];
        int t = t0 + i;
        if (p < Cq) { g_pos2[t] = p; slot[p] = t; }
        else        { g_pos2[t] = Cq - 1; g_w2[t] = 0.f; }
    }

    // occupied slot count for this expert (slots [0, cnt_e) are in use)
    if (tid == 0) {
        int tot = s_total1 + wsum[31];
        g_cnt[e] = tot < Cq ? tot : Cq;
    }
}

// ---------------- kernel 3: gather dispatched tokens -> fp16 ---------------
__global__ void gather_kernel(const float* __restrict__ x) {
    int row = blockIdx.x;               // 0..16383
    int tok = g_slot_token[row];
    __half2* o = (__half2*)(g_xd + (size_t)row * Dq);
    if (tok >= 0) {
        const float4* xi = (const float4*)(x + (size_t)tok * Dq);
        for (int i = threadIdx.x; i < Dq / 4; i += blockDim.x) {
            float4 v = xi[i];
            o[i * 2 + 0] = __floats2half2_rn(v.x, v.y);
            o[i * 2 + 1] = __floats2half2_rn(v.z, v.w);
        }
    } else {
        int e = row >> 11;
        int slotpos = row & (Cq - 1);
        int padded = (g_cnt[e] + 127) & ~127;
        if (slotpos >= padded) return;   // never read by GEMM1
        __half2 z = __floats2half2_rn(0.f, 0.f);
        for (int i = threadIdx.x; i < Dq / 4; i += blockDim.x) {
            o[i * 2 + 0] = z; o[i * 2 + 1] = z;
        }
    }
}

// ---------------- kernel 4: weight transpose fp32 -> fp16 ------------------
__global__ void transpose_k(const float* __restrict__ in, __half* __restrict__ outp,
                            int R, int Cc) {
    __shared__ float t[64][65];
    const int e = blockIdx.z;
    const float* ip = in + (size_t)e * R * Cc;
    __half* op = outp + (size_t)e * R * Cc;
    const int c0 = blockIdx.x * 64, r0 = blockIdx.y * 64;
    const int tx = threadIdx.x, ty = threadIdx.y;   // 32 x 8

#pragma unroll
    for (int j = 0; j < 64; j += 8) {
        t[ty + j][tx]      = ip[(size_t)(r0 + ty + j) * Cc + c0 + tx];
        t[ty + j][tx + 32] = ip[(size_t)(r0 + ty + j) * Cc + c0 + tx + 32];
    }
    __syncthreads();
#pragma unroll
    for (int j = 0; j < 64; j += 8) {
        int cl = ty + j;
        __half2 v = __floats2half2_rn(t[2 * tx][cl], t[2 * tx + 1][cl]);
        *(__half2*)(op + (size_t)(c0 + cl) * R + r0 + 2 * tx) = v;
    }
}

// ---------------- fp16 mma.sync GEMM (128x128x64, fragment double-buffer) --
// 8 warps (2x4 tiling, 64x32 warp tile); control in warp 0, bottom refill.
// Empty slot blocks (row >= cnt_e) early-return.
// Inner loop prefetches kk+1 fragments during kk MMAs (same MMA order -> same bits).
template <int KT, bool GELU, typename OT, int NTOT>
__global__ void __launch_bounds__(256, 1)
gemm_mma(const __grid_constant__ CUtensorMap tmA,
         const __grid_constant__ CUtensorMap tmB,
         const float* __restrict__ bias, OT* __restrict__ Out) {
    constexpr int S = 3;
    constexpr int TILE_B = 16384;          // 128 rows x 128B (64 fp16)
    extern __shared__ __align__(1024) char smem[];
    const uint32_t sb = smem_u32(smem);
    const int tid = threadIdx.x;
    const int wid = tid >> 5, lane = tid & 31;
    const int row0 = blockIdx.y * 128;
    const int col0 = blockIdx.x * 128;
    const int e = row0 >> 11;              // row0 / 2048

    // skip fully-empty slot blocks (slots are filled as a prefix per expert)
    if ((row0 & (Cq - 1)) >= g_cnt[e]) return;

    const uint32_t FULL0 = sb;             // full[s] = FULL0 + 16*s
    const uint32_t EMPT0 = sb + 8;         // empty[s] = EMPT0 + 16*s
    const uint32_t SA = sb + 1024;
    const uint32_t SB_ = sb + 1024 + S * TILE_B;

    if (tid == 0) {
#pragma unroll
        for (int s = 0; s < S; s++) {
            MBAR_INIT(FULL0 + 16 * s, 1);
            MBAR_INIT(EMPT0 + 16 * s, 8);   // one arrive per warp
        }
        FENCE_PROXY_ASYNC();                // order init before async-proxy TMA
    }
    __syncthreads();

    // warp tiling: 2 (M) x 4 (N); warp tile 64 x 32
    const int warp_m = wid >> 2, warp_n = wid & 3;
    const int m0 = warp_m * 64, n0 = warp_n * 32;
    const uint32_t sw = (uint32_t)(lane & 7) << 4;   // SW128 xor

    uint32_t aoff[4], boff[2];
#pragma unroll
    for (int mi = 0; mi < 4; mi++)
        aoff[mi] = (uint32_t)(m0 + mi * 16 + (lane & 15)) * 128;
#pragma unroll
    for (int p = 0; p < 2; p++)
        boff[p] = (uint32_t)(n0 + (2 * p + ((lane >> 4) & 1)) * 8 + (lane & 7)) * 128;
    const uint32_t kxA = ((lane >> 4) & 1) * 16;
    const uint32_t kxB = ((lane >> 3) & 1) * 16;

    float acc[4][4][4];
#pragma unroll
    for (int mi = 0; mi < 4; mi++)
#pragma unroll
        for (int ni = 0; ni < 4; ni++)
#pragma unroll
            for (int q = 0; q < 4; q++) acc[mi][ni][q] = 0.f;

    if (tid == 0) {
#pragma unroll
        for (int s = 0; s < S && s < KT; s++) {
            MBAR_EXPECT_TX(FULL0 + 16 * s, 2 * TILE_B);
            TMA_LD3D(SA + s * TILE_B, &tmA, s * 64, row0, 0, FULL0 + 16 * s);
            TMA_LD3D(SB_ + s * TILE_B, &tmB, s * 64, col0, e, FULL0 + 16 * s);
        }
    }

#pragma unroll 1
    for (int kt = 0; kt < KT; kt++) {
        const int st = kt % S;
        const int ph = (kt / S) & 1;
        MBAR_WAIT(FULL0 + 16 * st, ph);

        const uint32_t sa = SA + st * TILE_B;
        const uint32_t sbB = SB_ + st * TILE_B;

        // double-buffered fragments: load kk=0, then prefetch kk+1 during kk MMAs
        uint32_t a[2][4][4], b[2][4][2];
        {
            const uint32_t ka = kxA ^ sw;
            const uint32_t kb = kxB ^ sw;
#pragma unroll
            for (int mi = 0; mi < 4; mi++)
                LDSM4(a[0][mi][0], a[0][mi][1], a[0][mi][2], a[0][mi][3],
                      sa + aoff[mi] + ka);
#pragma unroll
            for (int p = 0; p < 2; p++) {
                uint32_t r0, r1, r2, r3;
                LDSM4(r0, r1, r2, r3, sbB + boff[p] + kb);
                b[0][2 * p][0] = r0; b[0][2 * p][1] = r1;
                b[0][2 * p + 1][0] = r2; b[0][2 * p + 1][1] = r3;
            }
        }
#pragma unroll
        for (int kk = 0; kk < 4; kk++) {
            const int cur = kk & 1, nxt = cur ^ 1;
            if (kk < 3) {
                const uint32_t ka = ((uint32_t)((kk + 1) * 32) + kxA) ^ sw;
                const uint32_t kb = ((uint32_t)((kk + 1) * 32) + kxB) ^ sw;
#pragma unroll
                for (int mi = 0; mi < 4; mi++)
                    LDSM4(a[nxt][mi][0], a[nxt][mi][1], a[nxt][mi][2], a[nxt][mi][3],
                          sa + aoff[mi] + ka);
#pragma unroll
                for (int p = 0; p < 2; p++) {
                    uint32_t r0, r1, r2, r3;
                    LDSM4(r0, r1, r2, r3, sbB + boff[p] + kb);
                    b[nxt][2 * p][0] = r0; b[nxt][2 * p][1] = r1;
                    b[nxt][2 * p + 1][0] = r2; b[nxt][2 * p + 1][1] = r3;
                }
            }
#pragma unroll
            for (int mi = 0; mi < 4; mi++)
#pragma unroll
                for (int ni = 0; ni < 4; ni++)
                    MMA16816(acc[mi][ni], a[cur][mi], b[cur][ni][0], b[cur][ni][1]);
        }
        if (lane == 0) MBAR_ARRIVE(EMPT0 + 16 * st);

        if (tid == 0) {
            int j = kt + S;
            if (j < KT) {
                MBAR_WAIT(EMPT0 + 16 * st, ph);
                MBAR_EXPECT_TX(FULL0 + 16 * st, 2 * TILE_B);
                TMA_LD3D(SA + st * TILE_B, &tmA, j * 64, row0, 0, FULL0 + 16 * st);
                TMA_LD3D(SB_ + st * TILE_B, &tmB, j * 64, col0, e, FULL0 + 16 * st);
            }
        }
    }

    // ---------------- epilogue ------------------------------------------
    const float* brow = bias + (size_t)e * NTOT;
#pragma unroll
    for (int mi = 0; mi < 4; mi++) {
#pragma unroll
        for (int ni = 0; ni < 4; ni++) {
            int col = col0 + n0 + ni * 8 + (lane & 3) * 2;
            float bz0 = brow[col], bz1 = brow[col + 1];
#pragma unroll
            for (int h = 0; h < 2; h++) {
                int row = row0 + m0 + mi * 16 + (lane >> 2) + h * 8;
                float v0 = acc[mi][ni][2 * h + 0] + bz0;
                float v1 = acc[mi][ni][2 * h + 1] + bz1;
                if (GELU) {
                    v0 = 0.5f * v0 * (1.f + erff(v0 * 0.70710678118654752f));
                    v1 = 0.5f * v1 * (1.f + erff(v1 * 0.70710678118654752f));
                }
                if (sizeof(OT) == 2) {
                    *(__half2*)((__half*)Out + (size_t)row * NTOT + col) =
                        __floats2half2_rn(v0, v1);
                } else {
                    *(float2*)((float*)Out + (size_t)row * NTOT + col) =
                        make_float2(v0, v1);
                }
            }
        }
    }
}

// ---------------- kernel 7: combine (128 thr, 2 float4/thread, MLP=4) ------
__global__ void combine_kernel(float* __restrict__ out) {
    int t = blockIdx.x;
    int i1 = g_idx1[t], i2 = g_idx2[t];
    float w1 = g_w1[t], w2 = g_w2[t];
    const float4* y1 = (const float4*)(g_ye + ((size_t)i1 * Cq + g_pos1[t]) * Dq);
    const float4* y2 = (const float4*)(g_ye + ((size_t)i2 * Cq + g_pos2[t]) * Dq);
    float4* o = (float4*)(out + (size_t)t * Dq);
    int j0 = threadIdx.x;
    int j1 = threadIdx.x + 128;
    float4 a0 = __ldg(y1 + j0), b0 = __ldg(y2 + j0);
    float4 a1 = __ldg(y1 + j1), b1 = __ldg(y2 + j1);
    float4 r0, r1;
    r0.x = w1 * a0.x + w2 * b0.x;  r0.y = w1 * a0.y + w2 * b0.y;
    r0.z = w1 * a0.z + w2 * b0.z;  r0.w = w1 * a0.w + w2 * b0.w;
    r1.x = w1 * a1.x + w2 * b1.x;  r1.y = w1 * a1.y + w2 * b1.y;
    r1.z = w1 * a1.z + w2 * b1.z;  r1.w = w1 * a1.w + w2 * b1.w;
    o[j0] = r0;
    o[j1] = r1;
}

// ---------------- host: tensor-map build + launch ---------------------------
typedef CUresult (*EncodeFn)(CUtensorMap*, CUtensorMapDataType, cuuint32_t, void*,
                             const cuuint64_t*, const cuuint64_t*, const cuuint32_t*,
                             const cuuint32_t*, CUtensorMapInterleave, CUtensorMapSwizzle,
                             CUtensorMapL2promotion, CUtensorMapFloatOOBfill);

static void enc_map(EncodeFn fn, CUtensorMap* m, void* p,
                    uint64_t d0, uint64_t d1, uint64_t d2) {
    cuuint64_t dims[3] = {d0, d1, d2};
    cuuint64_t str[2] = {d0 * 2, d0 * d1 * 2};   // fp16
    cuuint32_t box[3] = {64, 128, 1};            // 64 fp16 = 128B rows
    cuuint32_t es[3] = {1, 1, 1};
    fn(m, CU_TENSOR_MAP_DATA_TYPE_FLOAT16, 3, p, dims, str, box, es,
       CU_TENSOR_MAP_INTERLEAVE_NONE, CU_TENSOR_MAP_SWIZZLE_128B,
       CU_TENSOR_MAP_L2_PROMOTION_L2_128B, CU_TENSOR_MAP_FLOAT_OOB_FILL_NONE);
}

extern "C" void kernel_launch(void* const* d_in, const int* in_sizes, int n_in,
                              void* d_out, int out_size) {
    const float* x  = (const float*)d_in[0];
    const float* Wg = (const float*)d_in[1];
    const float* W1 = (const float*)d_in[2];
    const float* b1 = (const float*)d_in[3];
    const float* W2 = (const float*)d_in[4];
    const float* b2 = (const float*)d_in[5];
    float* out = (float*)d_out;

    __half *xd, *w1t, *w2t, *hbuf;
    float* yebuf;
    cudaGetSymbolAddress((void**)&xd,    g_xd);
    cudaGetSymbolAddress((void**)&w1t,   g_w1t);
    cudaGetSymbolAddress((void**)&w2t,   g_w2t);
    cudaGetSymbolAddress((void**)&hbuf,  g_h);
    cudaGetSymbolAddress((void**)&yebuf, g_ye);

    EncodeFn enc = nullptr;
    {
        void* fp = nullptr;
        cudaDriverEntryPointQueryResult qr;
        cudaGetDriverEntryPointByVersion("cuTensorMapEncodeTiled", &fp, 12000,
                                         cudaEnableDefault, &qr);
        enc = (EncodeFn)fp;
    }

    CUtensorMap tmA1, tmB1, tmA2, tmB2;
    enc_map(enc, &tmA1, xd,   Dq, ROWS_TOT, 1);   // [16384,1024] fp16
    enc_map(enc, &tmB1, w1t,  Dq, Fq, Eq);        // [E][4096][1024]
    enc_map(enc, &tmA2, hbuf, Fq, ROWS_TOT, 1);   // [16384,4096]
    enc_map(enc, &tmB2, w2t,  Fq, Dq, Eq);        // [E][1024][4096]

    constexpr int SMEM_SZ = 1024 + 3 * 2 * 16384;  // 99328
    cudaFuncSetAttribute(gemm_mma<Dq / 64, true, __half, Fq>,
                         cudaFuncAttributeMaxDynamicSharedMemorySize, SMEM_SZ);
    cudaFuncSetAttribute(gemm_mma<Fq / 64, false, float, Dq>,
                         cudaFuncAttributeMaxDynamicSharedMemorySize, SMEM_SZ);

    // 1) gating
    gate_kernel<<<Tq / 4, 128>>>(x, Wg);
    // 2) ordered per-expert scan (also writes g_cnt)
    scan_kernel<<<Eq, 1024>>>();
    // 3) gather dispatched tokens (fp16; zero-fill trimmed to padded boundary)
    gather_kernel<<<ROWS_TOT, 128>>>(x);
    // 4) weight transposes, exact grids
    {
        dim3 blk(32, 8);
        transpose_k<<<dim3(Fq / 64, Dq / 64, Eq), blk>>>(W1, w1t, Dq, Fq);
        transpose_k<<<dim3(Dq / 64, Fq / 64, Eq), blk>>>(W2, w2t, Fq, Dq);
    }
    // 5) GEMM1: h = gelu(xd @ W1^T + b1)   [16384, 4096] fp16 (empty blocks skipped)
    gemm_mma<Dq / 64, true, __half, Fq>
        <<<dim3(Fq / 128, ROWS_TOT / 128), 256, SMEM_SZ>>>(tmA1, tmB1, b1, hbuf);
    // 6) GEMM2: ye = h @ W2^T + b2         [16384, 1024] fp32 (empty blocks skipped)
    gemm_mma<Fq / 64, false, float, Dq>
        <<<dim3(Dq / 128, ROWS_TOT / 128), 256, SMEM_SZ>>>(tmA2, tmB2, b2, yebuf);
    // 7) combine
    combine_kernel<<<Tq, 128>>>(out);
}

// round 17
// speedup vs baseline: 2.4414x; 1.0559x over previous
#include <cuda_runtime.h>
#include <cuda.h>
#include <cuda_fp16.h>
#include <math.h>
#include <stdint.h>

// Problem constants
#define Bq 2
#define Sq 2048
#define Dq 1024
#define Fq 4096
#define Eq 8
#define Tq (Bq * Sq)            // 4096 tokens
#define Cq ((2 * 2 * Tq) / Eq)  // capacity = 2048
#define ROWS_TOT (Eq * Cq)      // 16384

// ---------------- scratch (device globals) --------------------------------
__device__ int    g_idx1[Tq];
__device__ int    g_idx2[Tq];
__device__ int    g_pos1[Tq];
__device__ int    g_pos2[Tq];
__device__ float  g_w1[Tq];
__device__ float  g_w2[Tq];
__device__ int    g_cnt[Eq];                          // occupied slots per expert
__device__ int    g_slot_token[ROWS_TOT];             // slot -> token (-1 empty)
__device__ __half g_xd [(size_t)ROWS_TOT * Dq];       // dispatched tokens fp16  32MB
__device__ __half g_w1t[(size_t)Eq * Fq * Dq];        // W1^T [E][F][D] fp16     64MB
__device__ __half g_w2t[(size_t)Eq * Dq * Fq];        // W2^T [E][D][F] fp16     64MB
__device__ __half g_h  [(size_t)ROWS_TOT * Fq];       // h fp16                 128MB
__device__ float  g_ye [(size_t)ROWS_TOT * Dq];       // ye fp32                 64MB

// ---------------- PTX helpers ----------------------------------------------
__device__ __forceinline__ uint32_t smem_u32(const void* p) {
    uint32_t a;
    asm("{ .reg .u64 t; cvta.to.shared.u64 t, %1; cvt.u32.u64 %0, t; }" : "=r"(a) : "l"(p));
    return a;
}

#define MBAR_INIT(a, c) \
    asm volatile("mbarrier.init.shared.b64 [%0], %1;" :: "r"(a), "r"(c) : "memory")
#define MBAR_EXPECT_TX(a, b) \
    asm volatile("mbarrier.arrive.expect_tx.shared.b64 _, [%0], %1;" :: "r"(a), "r"(b) : "memory")
#define MBAR_ARRIVE(a) \
    asm volatile("mbarrier.arrive.shared.b64 _, [%0];" :: "r"(a) : "memory")
#define FENCE_PROXY_ASYNC() \
    asm volatile("fence.proxy.async.shared::cta;" ::: "memory")

#define MBAR_WAIT(mb, ph) do {                                                  \
    uint32_t _m = (mb); uint32_t _p = (ph);                                     \
    asm volatile("{\n\t.reg .pred P1;\n\t"                                      \
        "WL_%=:\n\t"                                                            \
        "mbarrier.try_wait.parity.acquire.cta.shared::cta.b64 P1, [%0], %1, 0x989680;\n\t" \
        "@P1 bra.uni WD_%=;\n\t"                                                \
        "bra.uni WL_%=;\n\t"                                                    \
        "WD_%=:\n\t}"                                                           \
        :: "r"(_m), "r"(_p) : "memory");                                        \
} while (0)

#define TMA_LD3D(smaddr, tmap, cx, cy, cz, mb)                                  \
    asm volatile("cp.async.bulk.tensor.3d.shared::cta.global.tile.mbarrier::complete_tx::bytes " \
        "[%0], [%1, {%2, %3, %4}], [%5];"                                       \
        :: "r"((uint32_t)(smaddr)), "l"(tmap), "r"((int)(cx)), "r"((int)(cy)),  \
           "r"((int)(cz)), "r"((uint32_t)(mb)) : "memory")

#define LDSM4(r0, r1, r2, r3, addr)                                             \
    asm volatile("ldmatrix.sync.aligned.m8n8.x4.shared.b16 {%0,%1,%2,%3}, [%4];" \
        : "=r"(r0), "=r"(r1), "=r"(r2), "=r"(r3) : "r"(addr))

#define MMA16816(c, a, b0, b1)                                                  \
    asm volatile("mma.sync.aligned.m16n8k16.row.col.f32.f16.f16.f32 "           \
        "{%0,%1,%2,%3}, {%4,%5,%6,%7}, {%8,%9}, {%0,%1,%2,%3};"                 \
        : "+f"((c)[0]), "+f"((c)[1]), "+f"((c)[2]), "+f"((c)[3])                \
        : "r"((a)[0]), "r"((a)[1]), "r"((a)[2]), "r"((a)[3]), "r"(b0), "r"(b1))

// ---------------- kernel 1: gating ----------------------------------------
__global__ void gate_kernel(const float* __restrict__ x,
                            const float* __restrict__ Wg) {
    int t = blockIdx.x * (blockDim.x >> 5) + (threadIdx.x >> 5);
    int lane = threadIdx.x & 31;
    if (t >= Tq) return;

    float acc[Eq];
#pragma unroll
    for (int e = 0; e < Eq; e++) acc[e] = 0.f;
    const float* xr = x + (size_t)t * Dq;
    for (int d = lane; d < Dq; d += 32) {
        float xv = xr[d];
        const float* wr = Wg + (size_t)d * Eq;
#pragma unroll
        for (int e = 0; e < Eq; e++) acc[e] += xv * wr[e];
    }
#pragma unroll
    for (int e = 0; e < Eq; e++)
#pragma unroll
        for (int off = 16; off > 0; off >>= 1)
            acc[e] += __shfl_xor_sync(0xffffffffu, acc[e], off);
    if (lane == 0) {
        int i1 = 0; float l1 = acc[0];
#pragma unroll
        for (int e = 1; e < Eq; e++) if (acc[e] > l1) { l1 = acc[e]; i1 = e; }
        int i2 = -1; float l2 = -3.4e38f;
#pragma unroll
        for (int e = 0; e < Eq; e++) if (e != i1 && acc[e] > l2) { l2 = acc[e]; i2 = e; }
        float s = 0.f, g[Eq];
#pragma unroll
        for (int e = 0; e < Eq; e++) { g[e] = expf(acc[e] - l1); s += g[e]; }
        float g1 = g[i1] / s, g2 = g[i2] / s;
        float denom = g1 + g2 + 1e-9f;
        g_idx1[t] = i1; g_idx2[t] = i2;
        g_w1[t] = g1 / denom; g_w2[t] = g2 / denom;
    }
}

// ---------------- kernel 2: per-expert ordered scan ------------------------
__global__ void scan_kernel() {
    const int e = blockIdx.x;
    const int tid = threadIdx.x;
    const int lane = tid & 31, wid = tid >> 5;
    __shared__ int wsum[32];
    __shared__ int s_total1;

    int* slot = g_slot_token + e * Cq;
    for (int s = tid; s < Cq; s += 1024) slot[s] = -1;
    __syncthreads();

    const int t0 = tid * 4;

    int m1[4], loc1[4], cnt = 0;
#pragma unroll
    for (int i = 0; i < 4; i++) { m1[i] = (g_idx1[t0 + i] == e); loc1[i] = cnt; cnt += m1[i]; }
    int v = cnt;
#pragma unroll
    for (int off = 1; off < 32; off <<= 1) {
        int u = __shfl_up_sync(0xffffffffu, v, off);
        if (lane >= off) v += u;
    }
    if (lane == 31) wsum[wid] = v;
    __syncthreads();
    if (wid == 0) {
        int w = wsum[lane];
#pragma unroll
        for (int off = 1; off < 32; off <<= 1) {
            int u = __shfl_up_sync(0xffffffffu, w, off);
            if (lane >= off) w += u;
        }
        wsum[lane] = w;
    }
    __syncthreads();
    int base = (v - cnt) + (wid ? wsum[wid - 1] : 0);
    if (tid == 0) s_total1 = wsum[31];
    __syncthreads();
#pragma unroll
    for (int i = 0; i < 4; i++) if (m1[i]) {
        int p = base + loc1[i];
        int t = t0 + i;
        if (p < Cq) { g_pos1[t] = p; slot[p] = t; }
        else        { g_pos1[t] = Cq - 1; g_w1[t] = 0.f; }
    }

    int m2[4], loc2[4]; cnt = 0;
#pragma unroll
    for (int i = 0; i < 4; i++) { m2[i] = (g_idx2[t0 + i] == e); loc2[i] = cnt; cnt += m2[i]; }
    v = cnt;
#pragma unroll
    for (int off = 1; off < 32; off <<= 1) {
        int u = __shfl_up_sync(0xffffffffu, v, off);
        if (lane >= off) v += u;
    }
    if (lane == 31) wsum[wid] = v;
    __syncthreads();
    if (wid == 0) {
        int w = wsum[lane];
#pragma unroll
        for (int off = 1; off < 32; off <<= 1) {
            int u = __shfl_up_sync(0xffffffffu, w, off);
            if (lane >= off) w += u;
        }
        wsum[lane] = w;
    }
    __syncthreads();
    int base2 = s_total1 + (v - cnt) + (wid ? wsum[wid - 1] : 0);
#pragma unroll
    for (int i = 0; i < 4; i++) if (m2[i]) {
        int p = base2 + loc2[i];
        int t = t0 + i;
        if (p < Cq) { g_pos2[t] = p; slot[p] = t; }
        else        { g_pos2[t] = Cq - 1; g_w2[t] = 0.f; }
    }

    // occupied slot count for this expert (slots [0, cnt_e) are in use)
    if (tid == 0) {
        int tot = s_total1 + wsum[31];
        g_cnt[e] = tot < Cq ? tot : Cq;
    }
}

// ---------------- kernel 3: gather dispatched tokens -> fp16 ---------------
__global__ void gather_kernel(const float* __restrict__ x) {
    int row = blockIdx.x;               // 0..16383
    int tok = g_slot_token[row];
    __half2* o = (__half2*)(g_xd + (size_t)row * Dq);
    if (tok >= 0) {
        const float4* xi = (const float4*)(x + (size_t)tok * Dq);
        for (int i = threadIdx.x; i < Dq / 4; i += blockDim.x) {
            float4 v = xi[i];
            o[i * 2 + 0] = __floats2half2_rn(v.x, v.y);
            o[i * 2 + 1] = __floats2half2_rn(v.z, v.w);
        }
    } else {
        int e = row >> 11;
        int slotpos = row & (Cq - 1);
        int padded = (g_cnt[e] + 127) & ~127;
        if (slotpos >= padded) return;   // never read by GEMM1
        __half2 z = __floats2half2_rn(0.f, 0.f);
        for (int i = threadIdx.x; i < Dq / 4; i += blockDim.x) {
            o[i * 2 + 0] = z; o[i * 2 + 1] = z;
        }
    }
}

// ---------------- kernel 4: weight transpose fp32 -> fp16 ------------------
__global__ void transpose_k(const float* __restrict__ in, __half* __restrict__ outp,
                            int R, int Cc) {
    __shared__ float t[64][65];
    const int e = blockIdx.z;
    const float* ip = in + (size_t)e * R * Cc;
    __half* op = outp + (size_t)e * R * Cc;
    const int c0 = blockIdx.x * 64, r0 = blockIdx.y * 64;
    const int tx = threadIdx.x, ty = threadIdx.y;   // 32 x 8

#pragma unroll
    for (int j = 0; j < 64; j += 8) {
        t[ty + j][tx]      = ip[(size_t)(r0 + ty + j) * Cc + c0 + tx];
        t[ty + j][tx + 32] = ip[(size_t)(r0 + ty + j) * Cc + c0 + tx + 32];
    }
    __syncthreads();
#pragma unroll
    for (int j = 0; j < 64; j += 8) {
        int cl = ty + j;
        __half2 v = __floats2half2_rn(t[2 * tx][cl], t[2 * tx + 1][cl]);
        *(__half2*)(op + (size_t)(c0 + cl) * R + r0 + 2 * tx) = v;
    }
}

// ---------------- fp16 mma.sync GEMM (128x128x64, forced 2 CTAs/SM) --------
// 8 warps (2x4 tiling, 64x32 warp tile); control in warp 0, bottom refill.
// Empty slot blocks (row >= cnt_e) early-return.
// __launch_bounds__(256, 2): cap regs at 128 so TWO CTAs co-reside per SM.
template <int KT, bool GELU, typename OT, int NTOT>
__global__ void __launch_bounds__(256, 2)
gemm_mma(const __grid_constant__ CUtensorMap tmA,
         const __grid_constant__ CUtensorMap tmB,
         const float* __restrict__ bias, OT* __restrict__ Out) {
    constexpr int S = 3;
    constexpr int TILE_B = 16384;          // 128 rows x 128B (64 fp16)
    extern __shared__ __align__(1024) char smem[];
    const uint32_t sb = smem_u32(smem);
    const int tid = threadIdx.x;
    const int wid = tid >> 5, lane = tid & 31;
    const int row0 = blockIdx.y * 128;
    const int col0 = blockIdx.x * 128;
    const int e = row0 >> 11;              // row0 / 2048

    // skip fully-empty slot blocks (slots are filled as a prefix per expert)
    if ((row0 & (Cq - 1)) >= g_cnt[e]) return;

    const uint32_t FULL0 = sb;             // full[s] = FULL0 + 16*s
    const uint32_t EMPT0 = sb + 8;         // empty[s] = EMPT0 + 16*s
    const uint32_t SA = sb + 1024;
    const uint32_t SB_ = sb + 1024 + S * TILE_B;

    if (tid == 0) {
#pragma unroll
        for (int s = 0; s < S; s++) {
            MBAR_INIT(FULL0 + 16 * s, 1);
            MBAR_INIT(EMPT0 + 16 * s, 8);   // one arrive per warp
        }
        FENCE_PROXY_ASYNC();                // order init before async-proxy TMA
    }
    __syncthreads();

    // warp tiling: 2 (M) x 4 (N); warp tile 64 x 32
    const int warp_m = wid >> 2, warp_n = wid & 3;
    const int m0 = warp_m * 64, n0 = warp_n * 32;
    const uint32_t sw = (uint32_t)(lane & 7) << 4;   // SW128 xor

    uint32_t aoff[4], boff[2];
#pragma unroll
    for (int mi = 0; mi < 4; mi++)
        aoff[mi] = (uint32_t)(m0 + mi * 16 + (lane & 15)) * 128;
#pragma unroll
    for (int p = 0; p < 2; p++)
        boff[p] = (uint32_t)(n0 + (2 * p + ((lane >> 4) & 1)) * 8 + (lane & 7)) * 128;
    const uint32_t kxA = ((lane >> 4) & 1) * 16;
    const uint32_t kxB = ((lane >> 3) & 1) * 16;

    float acc[4][4][4];
#pragma unroll
    for (int mi = 0; mi < 4; mi++)
#pragma unroll
        for (int ni = 0; ni < 4; ni++)
#pragma unroll
            for (int q = 0; q < 4; q++) acc[mi][ni][q] = 0.f;

    if (tid == 0) {
#pragma unroll
        for (int s = 0; s < S && s < KT; s++) {
            MBAR_EXPECT_TX(FULL0 + 16 * s, 2 * TILE_B);
            TMA_LD3D(SA + s * TILE_B, &tmA, s * 64, row0, 0, FULL0 + 16 * s);
            TMA_LD3D(SB_ + s * TILE_B, &tmB, s * 64, col0, e, FULL0 + 16 * s);
        }
    }

#pragma unroll 1
    for (int kt = 0; kt < KT; kt++) {
        const int st = kt % S;
        const int ph = (kt / S) & 1;
        MBAR_WAIT(FULL0 + 16 * st, ph);

        const uint32_t sa = SA + st * TILE_B;
        const uint32_t sbB = SB_ + st * TILE_B;
#pragma unroll
        for (int kk = 0; kk < 4; kk++) {
            const uint32_t ka = ((uint32_t)(kk * 32) + kxA) ^ sw;
            const uint32_t kb = ((uint32_t)(kk * 32) + kxB) ^ sw;
            uint32_t a[4][4], b[4][2];
#pragma unroll
            for (int mi = 0; mi < 4; mi++)
                LDSM4(a[mi][0], a[mi][1], a[mi][2], a[mi][3], sa + aoff[mi] + ka);
#pragma unroll
            for (int p = 0; p < 2; p++) {
                uint32_t r0, r1, r2, r3;
                LDSM4(r0, r1, r2, r3, sbB + boff[p] + kb);
                b[2 * p][0] = r0; b[2 * p][1] = r1;
                b[2 * p + 1][0] = r2; b[2 * p + 1][1] = r3;
            }
#pragma unroll
            for (int mi = 0; mi < 4; mi++)
#pragma unroll
                for (int ni = 0; ni < 4; ni++)
                    MMA16816(acc[mi][ni], a[mi], b[ni][0], b[ni][1]);
        }
        if (lane == 0) MBAR_ARRIVE(EMPT0 + 16 * st);

        if (tid == 0) {
            int j = kt + S;
            if (j < KT) {
                MBAR_WAIT(EMPT0 + 16 * st, ph);
                MBAR_EXPECT_TX(FULL0 + 16 * st, 2 * TILE_B);
                TMA_LD3D(SA + st * TILE_B, &tmA, j * 64, row0, 0, FULL0 + 16 * st);
                TMA_LD3D(SB_ + st * TILE_B, &tmB, j * 64, col0, e, FULL0 + 16 * st);
            }
        }
    }

    // ---------------- epilogue ------------------------------------------
    const float* brow = bias + (size_t)e * NTOT;
#pragma unroll
    for (int mi = 0; mi < 4; mi++) {
#pragma unroll
        for (int ni = 0; ni < 4; ni++) {
            int col = col0 + n0 + ni * 8 + (lane & 3) * 2;
            float bz0 = brow[col], bz1 = brow[col + 1];
#pragma unroll
            for (int h = 0; h < 2; h++) {
                int row = row0 + m0 + mi * 16 + (lane >> 2) + h * 8;
                float v0 = acc[mi][ni][2 * h + 0] + bz0;
                float v1 = acc[mi][ni][2 * h + 1] + bz1;
                if (GELU) {
                    v0 = 0.5f * v0 * (1.f + erff(v0 * 0.70710678118654752f));
                    v1 = 0.5f * v1 * (1.f + erff(v1 * 0.70710678118654752f));
                }
                if (sizeof(OT) == 2) {
                    *(__half2*)((__half*)Out + (size_t)row * NTOT + col) =
                        __floats2half2_rn(v0, v1);
                } else {
                    *(float2*)((float*)Out + (size_t)row * NTOT + col) =
                        make_float2(v0, v1);
                }
            }
        }
    }
}

// ---------------- kernel 7: combine (128 thr, 2 float4/thread, MLP=4) ------
__global__ void combine_kernel(float* __restrict__ out) {
    int t = blockIdx.x;
    int i1 = g_idx1[t], i2 = g_idx2[t];
    float w1 = g_w1[t], w2 = g_w2[t];
    const float4* y1 = (const float4*)(g_ye + ((size_t)i1 * Cq + g_pos1[t]) * Dq);
    const float4* y2 = (const float4*)(g_ye + ((size_t)i2 * Cq + g_pos2[t]) * Dq);
    float4* o = (float4*)(out + (size_t)t * Dq);
    int j0 = threadIdx.x;
    int j1 = threadIdx.x + 128;
    float4 a0 = __ldg(y1 + j0), b0 = __ldg(y2 + j0);
    float4 a1 = __ldg(y1 + j1), b1 = __ldg(y2 + j1);
    float4 r0, r1;
    r0.x = w1 * a0.x + w2 * b0.x;  r0.y = w1 * a0.y + w2 * b0.y;
    r0.z = w1 * a0.z + w2 * b0.z;  r0.w = w1 * a0.w + w2 * b0.w;
    r1.x = w1 * a1.x + w2 * b1.x;  r1.y = w1 * a1.y + w2 * b1.y;
    r1.z = w1 * a1.z + w2 * b1.z;  r1.w = w1 * a1.w + w2 * b1.w;
    o[j0] = r0;
    o[j1] = r1;
}

// ---------------- host: tensor-map build + launch ---------------------------
typedef CUresult (*EncodeFn)(CUtensorMap*, CUtensorMapDataType, cuuint32_t, void*,
                             const cuuint64_t*, const cuuint64_t*, const cuuint32_t*,
                             const cuuint32_t*, CUtensorMapInterleave, CUtensorMapSwizzle,
                             CUtensorMapL2promotion, CUtensorMapFloatOOBfill);

static void enc_map(EncodeFn fn, CUtensorMap* m, void* p,
                    uint64_t d0, uint64_t d1, uint64_t d2) {
    cuuint64_t dims[3] = {d0, d1, d2};
    cuuint64_t str[2] = {d0 * 2, d0 * d1 * 2};   // fp16
    cuuint32_t box[3] = {64, 128, 1};            // 64 fp16 = 128B rows
    cuuint32_t es[3] = {1, 1, 1};
    fn(m, CU_TENSOR_MAP_DATA_TYPE_FLOAT16, 3, p, dims, str, box, es,
       CU_TENSOR_MAP_INTERLEAVE_NONE, CU_TENSOR_MAP_SWIZZLE_128B,
       CU_TENSOR_MAP_L2_PROMOTION_L2_128B, CU_TENSOR_MAP_FLOAT_OOB_FILL_NONE);
}

extern "C" void kernel_launch(void* const* d_in, const int* in_sizes, int n_in,
                              void* d_out, int out_size) {
    const float* x  = (const float*)d_in[0];
    const float* Wg = (const float*)d_in[1];
    const float* W1 = (const float*)d_in[2];
    const float* b1 = (const float*)d_in[3];
    const float* W2 = (const float*)d_in[4];
    const float* b2 = (const float*)d_in[5];
    float* out = (float*)d_out;

    __half *xd, *w1t, *w2t, *hbuf;
    float* yebuf;
    cudaGetSymbolAddress((void**)&xd,    g_xd);
    cudaGetSymbolAddress((void**)&w1t,   g_w1t);
    cudaGetSymbolAddress((void**)&w2t,   g_w2t);
    cudaGetSymbolAddress((void**)&hbuf,  g_h);
    cudaGetSymbolAddress((void**)&yebuf, g_ye);

    EncodeFn enc = nullptr;
    {
        void* fp = nullptr;
        cudaDriverEntryPointQueryResult qr;
        cudaGetDriverEntryPointByVersion("cuTensorMapEncodeTiled", &fp, 12000,
                                         cudaEnableDefault, &qr);
        enc = (EncodeFn)fp;
    }

    CUtensorMap tmA1, tmB1, tmA2, tmB2;
    enc_map(enc, &tmA1, xd,   Dq, ROWS_TOT, 1);   // [16384,1024] fp16
    enc_map(enc, &tmB1, w1t,  Dq, Fq, Eq);        // [E][4096][1024]
    enc_map(enc, &tmA2, hbuf, Fq, ROWS_TOT, 1);   // [16384,4096]
    enc_map(enc, &tmB2, w2t,  Fq, Dq, Eq);        // [E][1024][4096]

    constexpr int SMEM_SZ = 1024 + 3 * 2 * 16384;  // 99328 (<= 113KB for 2 CTAs)
    cudaFuncSetAttribute(gemm_mma<Dq / 64, true, __half, Fq>,
                         cudaFuncAttributeMaxDynamicSharedMemorySize, SMEM_SZ);
    cudaFuncSetAttribute(gemm_mma<Fq / 64, false, float, Dq>,
                         cudaFuncAttributeMaxDynamicSharedMemorySize, SMEM_SZ);

    // 1) gating
    gate_kernel<<<Tq / 4, 128>>>(x, Wg);
    // 2) ordered per-expert scan (also writes g_cnt)
    scan_kernel<<<Eq, 1024>>>();
    // 3) gather dispatched tokens (fp16; zero-fill trimmed to padded boundary)
    gather_kernel<<<ROWS_TOT, 128>>>(x);
    // 4) weight transposes, exact grids
    {
        dim3 blk(32, 8);
        transpose_k<<<dim3(Fq / 64, Dq / 64, Eq), blk>>>(W1, w1t, Dq, Fq);
        transpose_k<<<dim3(Dq / 64, Fq / 64, Eq), blk>>>(W2, w2t, Fq, Dq);
    }
    // 5) GEMM1: h = gelu(xd @ W1^T + b1)   [16384, 4096] fp16 (empty blocks skipped)
    gemm_mma<Dq / 64, true, __half, Fq>
        <<<dim3(Fq / 128, ROWS_TOT / 128), 256, SMEM_SZ>>>(tmA1, tmB1, b1, hbuf);
    // 6) GEMM2: ye = h @ W2^T + b2         [16384, 1024] fp32 (empty blocks skipped)
    gemm_mma<Fq / 64, false, float, Dq>
        <<<dim3(Dq / 128, ROWS_TOT / 128), 256, SMEM_SZ>>>(tmA2, tmB2, b2, yebuf);
    // 7) combine
    combine_kernel<<<Tq, 128>>>(out);
}